// round 10
// baseline (speedup 1.0000x reference)
#include <cuda_runtime.h>
#include <cuda_bf16.h>
#include <cstdint>
#include <math.h>

#define NN 100000
#define NP 100096   /* 391 * 256 */
#define DD 128
#define HH 2
#define EE 640000
#define NRB 391     /* row blocks of 256 */

// ---------------- scratch (device globals; no runtime allocation) ----------
__device__ float g_q[NP * DD];
__device__ float g_k[NP * DD];
__device__ float g_v[NP * DD];
__device__ float g_xw[NP * DD];
__device__ float g_base[NP * DD];
__device__ float g_ex[EE * HH];   // spill for deg>32 edges: (ex_h0, ex_h1)
__device__ float g_dis[NN];
__device__ int   g_deg[NN];
__device__ int   g_off[NN];
__device__ int   g_cur[NN];
__device__ int   g_es[EE];        // dst-sorted src indices
__device__ int   g_ctr;
__device__ __align__(16) __nv_bfloat16 g_xhi[NP * DD];
__device__ __align__(16) __nv_bfloat16 g_xlo[NP * DD];
__device__ __align__(16) __nv_bfloat16 g_whi[5 * DD * DD];  // transposed [which][n][k]
__device__ __align__(16) __nv_bfloat16 g_wlo[5 * DD * DD];

// ---------------- helpers ----------------
__device__ __forceinline__ uint32_t smem_u32(const void* p) {
    uint32_t a;
    asm("{ .reg .u64 t; cvta.to.shared.u64 t, %1; cvt.u32.u64 %0, t; }"
        : "=r"(a) : "l"(p));
    return a;
}
__device__ __forceinline__ void ldsm4(uint32_t& r0, uint32_t& r1, uint32_t& r2,
                                      uint32_t& r3, uint32_t addr) {
    asm volatile("ldmatrix.sync.aligned.m8n8.x4.shared.b16 {%0,%1,%2,%3}, [%4];"
                 : "=r"(r0), "=r"(r1), "=r"(r2), "=r"(r3) : "r"(addr));
}
__device__ __forceinline__ void mma16816(float* c, const uint32_t* a,
                                         uint32_t b0, uint32_t b1) {
    asm volatile(
        "mma.sync.aligned.m16n8k16.row.col.f32.bf16.bf16.f32 "
        "{%0,%1,%2,%3}, {%4,%5,%6,%7}, {%8,%9}, {%0,%1,%2,%3};"
        : "+f"(c[0]), "+f"(c[1]), "+f"(c[2]), "+f"(c[3])
        : "r"(a[0]), "r"(a[1]), "r"(a[2]), "r"(a[3]), "r"(b0), "r"(b1));
}

// ---------------- K0: init scratch ----------------
__global__ void k_init() {
    int i = blockIdx.x * blockDim.x + threadIdx.x;
    if (i < NN) { g_deg[i] = 0; g_cur[i] = 0; }
    if (i == 0) g_ctr = 0;
}

// ---------------- K_deg: degree count ----------------
__global__ void k_deg(const int* __restrict__ ei) {
    int e = blockIdx.x * blockDim.x + threadIdx.x;
    if (e >= EE) return;
    atomicAdd(&g_deg[__ldg(ei + EE + e)], 1);
}

// ---------------- K_node: offsets (warp-aggregated alloc) + dis ----------
__global__ void k_node() {
    int i = blockIdx.x * blockDim.x + threadIdx.x;
    int lane = threadIdx.x & 31;
    int d = (i < NN) ? g_deg[i] : 0;
    int incl = d;
#pragma unroll
    for (int o = 1; o < 32; o <<= 1) {
        int n = __shfl_up_sync(0xffffffffu, incl, o);
        if (lane >= o) incl += n;
    }
    int base = 0;
    if (lane == 31) base = atomicAdd(&g_ctr, incl);
    base = __shfl_sync(0xffffffffu, base, 31);
    if (i < NN) {
        g_off[i] = base + incl - d;
        g_dis[i] = rsqrtf((float)d + 1.0f);
    }
}

// ---------------- K_scatter: build dst-sorted src list ----------------
__global__ void k_scatter(const int* __restrict__ ei) {
    int e = blockIdx.x * blockDim.x + threadIdx.x;
    if (e >= EE) return;
    int dst = __ldg(ei + EE + e);
    int pos = g_off[dst] + atomicAdd(&g_cur[dst], 1);
    g_es[pos] = __ldg(ei + e);
}

// ---------------- K_prep: hi/lo bf16 split of x (padded) ----------------
__global__ void k_prep_x(const float* __restrict__ x) {
    int i = blockIdx.x * blockDim.x + threadIdx.x;  // per 4 elems
    if (i >= NP * DD / 4) return;
    float4 v = make_float4(0.f, 0.f, 0.f, 0.f);
    if (i < NN * DD / 4) v = ((const float4*)x)[i];
    float a[4] = {v.x, v.y, v.z, v.w};
    unsigned short h[4], l[4];
#pragma unroll
    for (int j = 0; j < 4; j++) {
        __nv_bfloat16 hb = __float2bfloat16(a[j]);
        __nv_bfloat16 lb = __float2bfloat16(a[j] - __bfloat162float(hb));
        h[j] = __bfloat16_as_ushort(hb);
        l[j] = __bfloat16_as_ushort(lb);
    }
    ((ushort4*)g_xhi)[i] = make_ushort4(h[0], h[1], h[2], h[3]);
    ((ushort4*)g_xlo)[i] = make_ushort4(l[0], l[1], l[2], l[3]);
}

// ---------------- K_prep: transpose + hi/lo split of the 5 weights -------
__global__ void k_prep_w(const float* __restrict__ Wq, const float* __restrict__ Wk,
                         const float* __restrict__ Wv, const float* __restrict__ Ws,
                         const float* __restrict__ Wg) {
    int i = blockIdx.x * blockDim.x + threadIdx.x;
    if (i >= 5 * DD * DD) return;
    int which = i >> 14;
    int r = i & 16383;
    int n = r >> 7, k = r & 127;
    const float* W;
    switch (which) {
        case 0: W = Wq; break; case 1: W = Wk; break; case 2: W = Wv; break;
        case 3: W = Ws; break; default: W = Wg; break;
    }
    float v = W[k * DD + n];  // transposed: Wt[n][k] = W[k][n]
    __nv_bfloat16 hb = __float2bfloat16(v);
    __nv_bfloat16 lb = __float2bfloat16(v - __bfloat162float(hb));
    g_whi[i] = hb;
    g_wlo[i] = lb;
}

// ---------------- swizzled tile loaders (512 threads) ---------------------
__device__ __forceinline__ void load_x_tile(char* dst, const __nv_bfloat16* src, int t) {
#pragma unroll
    for (int i = 0; i < 8; i++) {
        int idx = i * 512 + t;
        int row = idx >> 4;
        int kc = idx & 15;
        uint32_t off = (uint32_t)(row * 256 + ((kc ^ (row & 7)) << 4));
        *(uint4*)(dst + off) = *(const uint4*)((const char*)src + row * 256 + kc * 16);
    }
}
__device__ __forceinline__ void load_w_tile(char* dst, const __nv_bfloat16* src, int t) {
#pragma unroll
    for (int i = 0; i < 4; i++) {
        int idx = i * 512 + t;
        int row = idx >> 4;
        int kc = idx & 15;
        uint32_t off = (uint32_t)(row * 256 + ((kc ^ (row & 7)) << 4));
        *(uint4*)(dst + off) = *(const uint4*)((const char*)src + row * 256 + kc * 16);
    }
}

// ---------------- K1: mma.sync GEMM, software-pipelined ----------------
// grid = (NRB, 5); block tile 256x128; 16 warps as 8x2; warp tile 32x64.
// Double-buffered A fragments across s-steps, B fragments across p-steps.
#define GS_XHI 0
#define GS_XLO 65536
#define GS_WHI 131072
#define GS_WLO 163840
#define GSMEM  196608

__global__ void __launch_bounds__(512, 1)
k_gemm_mma(const float* __restrict__ x,
           const float* __restrict__ bq, const float* __restrict__ bk,
           const float* __restrict__ bv, const float* __restrict__ bs) {
    extern __shared__ char smem[];
    uint32_t sb = smem_u32(smem);
    const int t = threadIdx.x;
    const int w = t >> 5, lane = t & 31;
    const int wr = w >> 1;
    const int wc = w & 1;
    const int row0 = blockIdx.x * 256;
    const int which = blockIdx.y;

    load_x_tile(smem + GS_XHI, g_xhi + (size_t)row0 * DD, t);
    load_x_tile(smem + GS_XLO, g_xlo + (size_t)row0 * DD, t);
    load_w_tile(smem + GS_WHI, g_whi + (size_t)which * DD * DD, t);
    load_w_tile(smem + GS_WLO, g_wlo + (size_t)which * DD * DD, t);
    __syncthreads();

    const int sub = lane >> 3;
    const int a_row = 32 * wr + (lane & 7) + ((sub & 1) << 3);
    const int a_kc2 = sub >> 1;
    const int ar7 = a_row & 7;
    const uint32_t a_off0 = sb + GS_XHI + (uint32_t)(a_row * 256);
    const uint32_t a_off1 = sb + GS_XHI + (uint32_t)((a_row + 16) * 256);
    const uint32_t a_loff0 = a_off0 + (GS_XLO - GS_XHI);
    const uint32_t a_loff1 = a_off1 + (GS_XLO - GS_XHI);
    const int b_n = 64 * wc + (lane & 7) + ((sub >> 1) << 3);
    const int b_kc2 = sub & 1;
    const int bn7 = b_n & 7;
    const uint32_t b_hoff = sb + GS_WHI + (uint32_t)(b_n * 256);
    const uint32_t b_loff = sb + GS_WLO + (uint32_t)(b_n * 256);

    float acc[2][8][4];
#pragma unroll
    for (int i = 0; i < 2; i++)
#pragma unroll
        for (int j = 0; j < 8; j++)
#pragma unroll
            for (int q = 0; q < 4; q++) acc[i][j][q] = 0.f;

    uint32_t ah0[2][4], ah1[2][4], al0[2][4], al1[2][4];
    uint32_t bh[2][4], bl[2][4];

    // prologue: A fragments for s=0, B_hi for (s=0, p=0)
    {
        const uint32_t akc = ((uint32_t)((a_kc2) ^ ar7)) << 4;  // s=0
        ldsm4(ah0[0][0], ah0[0][1], ah0[0][2], ah0[0][3], a_off0 + akc);
        ldsm4(ah1[0][0], ah1[0][1], ah1[0][2], ah1[0][3], a_off1 + akc);
        ldsm4(al0[0][0], al0[0][1], al0[0][2], al0[0][3], a_loff0 + akc);
        ldsm4(al1[0][0], al1[0][1], al1[0][2], al1[0][3], a_loff1 + akc);
        const uint32_t bkc = ((uint32_t)((b_kc2) ^ bn7)) << 4;  // s=0
        ldsm4(bh[0][0], bh[0][1], bh[0][2], bh[0][3], b_hoff + bkc);
    }

#pragma unroll
    for (int s = 0; s < 8; s++) {
        const int cs = s & 1, ns = cs ^ 1;
        const uint32_t bkc = ((uint32_t)((2 * s + b_kc2) ^ bn7)) << 4;
        const uint32_t bkc_n = ((uint32_t)((2 * (s + 1) + b_kc2) ^ bn7)) << 4;
        // prefetch A for s+1
        if (s < 7) {
            const uint32_t akc_n = ((uint32_t)((2 * (s + 1) + a_kc2) ^ ar7)) << 4;
            ldsm4(ah0[ns][0], ah0[ns][1], ah0[ns][2], ah0[ns][3], a_off0 + akc_n);
            ldsm4(ah1[ns][0], ah1[ns][1], ah1[ns][2], ah1[ns][3], a_off1 + akc_n);
            ldsm4(al0[ns][0], al0[ns][1], al0[ns][2], al0[ns][3], a_loff0 + akc_n);
            ldsm4(al1[ns][0], al1[ns][1], al1[ns][2], al1[ns][3], a_loff1 + akc_n);
        }
#pragma unroll
        for (int p = 0; p < 4; p++) {
            const int cp = p & 1, np = cp ^ 1;
            const uint32_t poff = (uint32_t)(p * 4096);
            // load B_lo for current p; prefetch B_hi for next p (or next s)
            ldsm4(bl[cp][0], bl[cp][1], bl[cp][2], bl[cp][3], b_loff + poff + bkc);
            if (p < 3) {
                ldsm4(bh[np][0], bh[np][1], bh[np][2], bh[np][3],
                      b_hoff + poff + 4096 + bkc);
            } else if (s < 7) {
                ldsm4(bh[np][0], bh[np][1], bh[np][2], bh[np][3], b_hoff + bkc_n);
            }
            // 12 MMAs
            mma16816(acc[0][2 * p],     ah0[cs], bh[cp][0], bh[cp][1]);
            mma16816(acc[0][2 * p + 1], ah0[cs], bh[cp][2], bh[cp][3]);
            mma16816(acc[1][2 * p],     ah1[cs], bh[cp][0], bh[cp][1]);
            mma16816(acc[1][2 * p + 1], ah1[cs], bh[cp][2], bh[cp][3]);
            mma16816(acc[0][2 * p],     al0[cs], bh[cp][0], bh[cp][1]);
            mma16816(acc[0][2 * p + 1], al0[cs], bh[cp][2], bh[cp][3]);
            mma16816(acc[1][2 * p],     al1[cs], bh[cp][0], bh[cp][1]);
            mma16816(acc[1][2 * p + 1], al1[cs], bh[cp][2], bh[cp][3]);
            mma16816(acc[0][2 * p],     ah0[cs], bl[cp][0], bl[cp][1]);
            mma16816(acc[0][2 * p + 1], ah0[cs], bl[cp][2], bl[cp][3]);
            mma16816(acc[1][2 * p],     ah1[cs], bl[cp][0], bl[cp][1]);
            mma16816(acc[1][2 * p + 1], ah1[cs], bl[cp][2], bl[cp][3]);
        }
    }

    float* out;
    const float* bias;
    switch (which) {
        case 0: out = g_q;    bias = bq; break;
        case 1: out = g_k;    bias = bk; break;
        case 2: out = g_v;    bias = bv; break;
        case 3: out = g_base; bias = bs; break;
        default: out = g_xw;  bias = 0;  break;
    }
    const int rbase = row0 + 32 * wr + (lane >> 2);
    const int colb = 64 * wc + (lane & 3) * 2;
#pragma unroll
    for (int rg = 0; rg < 2; rg++) {
        const int r0i = rbase + 16 * rg;
        const bool ok0 = r0i < NN, ok1 = (r0i + 8) < NN;
#pragma unroll
        for (int nt = 0; nt < 8; nt++) {
            int col = nt * 8 + colb;
            float bx = 0.f, by = 0.f;
            if (bias) { bx = __ldg(bias + col); by = __ldg(bias + col + 1); }
            float2 v0 = make_float2(acc[rg][nt][0] + bx, acc[rg][nt][1] + by);
            float2 v1 = make_float2(acc[rg][nt][2] + bx, acc[rg][nt][3] + by);
            if (which == 3) {
                if (ok0) {
                    float2 xv = *(const float2*)(x + (size_t)r0i * DD + col);
                    v0.x += xv.x; v0.y += xv.y;
                }
                if (ok1) {
                    float2 xv = *(const float2*)(x + (size_t)(r0i + 8) * DD + col);
                    v1.x += xv.x; v1.y += xv.y;
                }
            }
            if (ok0) *(float2*)(out + (size_t)r0i * DD + col) = v0;
            if (ok1) *(float2*)(out + (size_t)(r0i + 8) * DD + col) = v1;
        }
    }
}

// ---------------- K2: fused per-node attention + GCN + LN + ReLU ----------
// warp per node; lane covers channels [4*lane, 4*lane+3]; head = lane>>4.
// GCN accumulation merged into loop 1; chunk-0 ex kept in registers.
__global__ void __launch_bounds__(256)
k_fused(const float* __restrict__ bgcn,
        const float* __restrict__ gamma,
        const float* __restrict__ beta,
        float* __restrict__ out) {
    int i = blockIdx.x * 8 + (threadIdx.x >> 5);
    if (i >= NN) return;
    const int lane = threadIdx.x & 31;
    const int c4 = lane * 4;
    const int head = lane >> 4;

    const int off = g_off[i];
    const int deg = g_deg[i];
    const int end = off + deg;
    const float dis_i = g_dis[i];

    float4 qv = *(const float4*)(g_q + (size_t)i * DD + c4);

    float den = 0.f;
    float4 acc = make_float4(0.f, 0.f, 0.f, 0.f);
    float2 myex0 = make_float2(0.f, 0.f);
    int myidx0 = 0;

    // ---- loop 1: logits -> ex + den, and GCN (w * xw) accumulation ----
    for (int base = off; base < end; base += 32) {
        int cnt = min(32, end - base);
        int myidx = (lane < cnt) ? __ldg(g_es + base + lane) : 0;
        if (base == off) myidx0 = myidx;
        for (int j = 0; j < cnt; j++) {
            int src = __shfl_sync(0xffffffffu, myidx, j);
            float4 kv = *(const float4*)(g_k + (size_t)src * DD + c4);
            float4 xv = *(const float4*)(g_xw + (size_t)src * DD + c4);
            float s = qv.x * kv.x + qv.y * kv.y + qv.z * kv.z + qv.w * kv.w;
            s += __shfl_xor_sync(0xffffffffu, s, 8);
            s += __shfl_xor_sync(0xffffffffu, s, 4);
            s += __shfl_xor_sync(0xffffffffu, s, 2);
            s += __shfl_xor_sync(0xffffffffu, s, 1);
            float ex = __expf(s * 0.125f);   // / sqrt(64)
            den += ex;                        // per-lane copy of its head's den
            float w = g_dis[src] * dis_i;
            acc.x += w * xv.x; acc.y += w * xv.y;
            acc.z += w * xv.z; acc.w += w * xv.w;
            float e0 = __shfl_sync(0xffffffffu, ex, 0);
            float e1 = __shfl_sync(0xffffffffu, ex, 16);
            if (base == off) {
                if (lane == j) myex0 = make_float2(e0, e1);
            } else if (lane == 0) {
                *(float2*)(g_ex + (size_t)(base + j) * 2) = make_float2(e0, e1);
            }
        }
    }
    den += 1e-16f;
    float rden = 1.0f / den;

    // ---- loop 2: alpha-weighted V accumulation ----
    for (int base = off; base < end; base += 32) {
        int cnt = min(32, end - base);
        int myidx;
        float2 myex;
        if (base == off) {
            myidx = myidx0;
            myex = myex0;
        } else {
            myidx = (lane < cnt) ? __ldg(g_es + base + lane) : 0;
            myex = (lane < cnt) ? *(const float2*)(g_ex + (size_t)(base + lane) * 2)
                                : make_float2(0.f, 0.f);
        }
        for (int j = 0; j < cnt; j++) {
            int src = __shfl_sync(0xffffffffu, myidx, j);
            float e0 = __shfl_sync(0xffffffffu, myex.x, j);
            float e1 = __shfl_sync(0xffffffffu, myex.y, j);
            float alpha = (head ? e1 : e0) * rden;
            float4 vv = *(const float4*)(g_v + (size_t)src * DD + c4);
            acc.x += alpha * vv.x; acc.y += alpha * vv.y;
            acc.z += alpha * vv.z; acc.w += alpha * vv.w;
        }
    }

    // ---- finalize: base + self-loop + LayerNorm + ReLU ----
    float4 b = *(const float4*)(g_base + (size_t)i * DD + c4);
    float4 xv = *(const float4*)(g_xw + (size_t)i * DD + c4);
    float4 bg = *(const float4*)(bgcn + c4);
    float d2 = dis_i * dis_i;

    float v0 = b.x + acc.x + d2 * xv.x + bg.x;
    float v1 = b.y + acc.y + d2 * xv.y + bg.y;
    float v2 = b.z + acc.z + d2 * xv.z + bg.z;
    float v3 = b.w + acc.w + d2 * xv.w + bg.w;

    float s = v0 + v1 + v2 + v3;
#pragma unroll
    for (int o = 16; o > 0; o >>= 1) s += __shfl_xor_sync(0xffffffffu, s, o);
    float mu = s * (1.0f / 128.0f);

    float d0 = v0 - mu, d1 = v1 - mu, d2_ = v2 - mu, d3 = v3 - mu;
    float sq = d0 * d0 + d1 * d1 + d2_ * d2_ + d3 * d3;
#pragma unroll
    for (int o = 16; o > 0; o >>= 1) sq += __shfl_xor_sync(0xffffffffu, sq, o);
    float inv = rsqrtf(sq * (1.0f / 128.0f) + 1e-5f);

    float4 g = *(const float4*)(gamma + c4);
    float4 be = *(const float4*)(beta + c4);
    float4 o4;
    o4.x = fmaxf(d0 * inv * g.x + be.x, 0.0f);
    o4.y = fmaxf(d1 * inv * g.y + be.y, 0.0f);
    o4.z = fmaxf(d2_ * inv * g.z + be.z, 0.0f);
    o4.w = fmaxf(d3 * inv * g.w + be.w, 0.0f);
    *(float4*)(out + (size_t)i * DD + c4) = o4;
}

// ---------------- launch ----------------
extern "C" void kernel_launch(void* const* d_in, const int* in_sizes, int n_in,
                              void* d_out, int out_size) {
    const float* x     = (const float*)d_in[0];
    const int*   ei    = (const int*)d_in[1];
    const float* Wq    = (const float*)d_in[2];
    const float* bq    = (const float*)d_in[3];
    const float* Wk    = (const float*)d_in[4];
    const float* bk    = (const float*)d_in[5];
    const float* Wv    = (const float*)d_in[6];
    const float* bv    = (const float*)d_in[7];
    const float* Wskip = (const float*)d_in[8];
    const float* bskip = (const float*)d_in[9];
    const float* Wgcn  = (const float*)d_in[10];
    const float* bgcn  = (const float*)d_in[11];
    const float* gamma = (const float*)d_in[12];
    const float* beta  = (const float*)d_in[13];
    float* out = (float*)d_out;

    static int smem_set = 0;
    if (!smem_set) {
        cudaFuncSetAttribute(k_gemm_mma,
                             cudaFuncAttributeMaxDynamicSharedMemorySize, GSMEM);
        smem_set = 1;
    }

    k_init<<<(NN + 255) / 256, 256>>>();
    k_prep_x<<<(NP * DD / 4 + 255) / 256, 256>>>(x);
    k_prep_w<<<(5 * DD * DD + 255) / 256, 256>>>(Wq, Wk, Wv, Wskip, Wgcn);
    k_deg<<<(EE + 255) / 256, 256>>>(ei);
    k_node<<<(NN + 255) / 256, 256>>>();
    k_scatter<<<(EE + 255) / 256, 256>>>(ei);
    dim3 ggrid(NRB, 5);
    k_gemm_mma<<<ggrid, 512, GSMEM>>>(x, bq, bk, bv, bskip);
    k_fused<<<(NN + 7) / 8, 256>>>(bgcn, gamma, beta, out);
}

// round 11
// speedup vs baseline: 1.0005x; 1.0005x over previous
#include <cuda_runtime.h>
#include <cuda_bf16.h>
#include <cstdint>
#include <math.h>

#define NN 100000
#define NP 100096   /* 391 * 256 */
#define DD 128
#define HH 2
#define EE 640000
#define NRB 391     /* row blocks of 256 */

// ---------------- scratch (device globals; no runtime allocation) ----------
__device__ float g_q[NP * DD];
__device__ float g_k[NP * DD];
__device__ float g_v[NP * DD];
__device__ float g_xw[NP * DD];
__device__ float g_base[NP * DD];
__device__ float g_ex[EE * HH];   // spill for deg>32 edges: (ex_h0, ex_h1)
__device__ float g_dis[NN];
__device__ int   g_deg[NN];
__device__ int   g_off[NN];
__device__ int   g_cur[NN];
__device__ int   g_es[EE];        // dst-sorted src indices
__device__ int   g_ctr;
__device__ __align__(16) __nv_bfloat16 g_xhi[NP * DD];
__device__ __align__(16) __nv_bfloat16 g_xlo[NP * DD];
__device__ __align__(16) __nv_bfloat16 g_whi[5 * DD * DD];  // transposed [which][n][k]
__device__ __align__(16) __nv_bfloat16 g_wlo[5 * DD * DD];

// ---------------- helpers ----------------
__device__ __forceinline__ uint32_t smem_u32(const void* p) {
    uint32_t a;
    asm("{ .reg .u64 t; cvta.to.shared.u64 t, %1; cvt.u32.u64 %0, t; }"
        : "=r"(a) : "l"(p));
    return a;
}
__device__ __forceinline__ void ldsm4(uint32_t& r0, uint32_t& r1, uint32_t& r2,
                                      uint32_t& r3, uint32_t addr) {
    asm volatile("ldmatrix.sync.aligned.m8n8.x4.shared.b16 {%0,%1,%2,%3}, [%4];"
                 : "=r"(r0), "=r"(r1), "=r"(r2), "=r"(r3) : "r"(addr));
}
__device__ __forceinline__ void mma16816(float* c, const uint32_t* a,
                                         uint32_t b0, uint32_t b1) {
    asm volatile(
        "mma.sync.aligned.m16n8k16.row.col.f32.bf16.bf16.f32 "
        "{%0,%1,%2,%3}, {%4,%5,%6,%7}, {%8,%9}, {%0,%1,%2,%3};"
        : "+f"(c[0]), "+f"(c[1]), "+f"(c[2]), "+f"(c[3])
        : "r"(a[0]), "r"(a[1]), "r"(a[2]), "r"(a[3]), "r"(b0), "r"(b1));
}

// ---------------- K0: init scratch ----------------
__global__ void k_init() {
    int i = blockIdx.x * blockDim.x + threadIdx.x;
    if (i < NN) { g_deg[i] = 0; g_cur[i] = 0; }
    if (i == 0) g_ctr = 0;
}

// ---------------- K_deg: degree count ----------------
__global__ void k_deg(const int* __restrict__ ei) {
    int e = blockIdx.x * blockDim.x + threadIdx.x;
    if (e >= EE) return;
    atomicAdd(&g_deg[__ldg(ei + EE + e)], 1);
}

// ---------------- K_node: offsets (warp-aggregated alloc) + dis ----------
__global__ void k_node() {
    int i = blockIdx.x * blockDim.x + threadIdx.x;
    int lane = threadIdx.x & 31;
    int d = (i < NN) ? g_deg[i] : 0;
    int incl = d;
#pragma unroll
    for (int o = 1; o < 32; o <<= 1) {
        int n = __shfl_up_sync(0xffffffffu, incl, o);
        if (lane >= o) incl += n;
    }
    int base = 0;
    if (lane == 31) base = atomicAdd(&g_ctr, incl);
    base = __shfl_sync(0xffffffffu, base, 31);
    if (i < NN) {
        g_off[i] = base + incl - d;
        g_dis[i] = rsqrtf((float)d + 1.0f);
    }
}

// ---------------- K_scatter: build dst-sorted src list ----------------
__global__ void k_scatter(const int* __restrict__ ei) {
    int e = blockIdx.x * blockDim.x + threadIdx.x;
    if (e >= EE) return;
    int dst = __ldg(ei + EE + e);
    int pos = g_off[dst] + atomicAdd(&g_cur[dst], 1);
    g_es[pos] = __ldg(ei + e);
}

// ---------------- K_prep: hi/lo bf16 split of x (padded) ----------------
__global__ void k_prep_x(const float* __restrict__ x) {
    int i = blockIdx.x * blockDim.x + threadIdx.x;  // per 4 elems
    if (i >= NP * DD / 4) return;
    float4 v = make_float4(0.f, 0.f, 0.f, 0.f);
    if (i < NN * DD / 4) v = ((const float4*)x)[i];
    float a[4] = {v.x, v.y, v.z, v.w};
    unsigned short h[4], l[4];
#pragma unroll
    for (int j = 0; j < 4; j++) {
        __nv_bfloat16 hb = __float2bfloat16(a[j]);
        __nv_bfloat16 lb = __float2bfloat16(a[j] - __bfloat162float(hb));
        h[j] = __bfloat16_as_ushort(hb);
        l[j] = __bfloat16_as_ushort(lb);
    }
    ((ushort4*)g_xhi)[i] = make_ushort4(h[0], h[1], h[2], h[3]);
    ((ushort4*)g_xlo)[i] = make_ushort4(l[0], l[1], l[2], l[3]);
}

// ---------------- K_prep: transpose + hi/lo split of the 5 weights -------
__global__ void k_prep_w(const float* __restrict__ Wq, const float* __restrict__ Wk,
                         const float* __restrict__ Wv, const float* __restrict__ Ws,
                         const float* __restrict__ Wg) {
    int i = blockIdx.x * blockDim.x + threadIdx.x;
    if (i >= 5 * DD * DD) return;
    int which = i >> 14;
    int r = i & 16383;
    int n = r >> 7, k = r & 127;
    const float* W;
    switch (which) {
        case 0: W = Wq; break; case 1: W = Wk; break; case 2: W = Wv; break;
        case 3: W = Ws; break; default: W = Wg; break;
    }
    float v = W[k * DD + n];  // transposed: Wt[n][k] = W[k][n]
    __nv_bfloat16 hb = __float2bfloat16(v);
    __nv_bfloat16 lb = __float2bfloat16(v - __bfloat162float(hb));
    g_whi[i] = hb;
    g_wlo[i] = lb;
}

// ---------------- swizzled tile loaders (512 threads) ---------------------
__device__ __forceinline__ void load_x_tile(char* dst, const __nv_bfloat16* src, int t) {
#pragma unroll
    for (int i = 0; i < 8; i++) {
        int idx = i * 512 + t;
        int row = idx >> 4;
        int kc = idx & 15;
        uint32_t off = (uint32_t)(row * 256 + ((kc ^ (row & 7)) << 4));
        *(uint4*)(dst + off) = *(const uint4*)((const char*)src + row * 256 + kc * 16);
    }
}
__device__ __forceinline__ void load_w_tile(char* dst, const __nv_bfloat16* src, int t) {
#pragma unroll
    for (int i = 0; i < 4; i++) {
        int idx = i * 512 + t;
        int row = idx >> 4;
        int kc = idx & 15;
        uint32_t off = (uint32_t)(row * 256 + ((kc ^ (row & 7)) << 4));
        *(uint4*)(dst + off) = *(const uint4*)((const char*)src + row * 256 + kc * 16);
    }
}

// ---------------- K1: mma.sync GEMM, one weight per block (R8, unchanged) -
#define GS_XHI 0
#define GS_XLO 65536
#define GS_WHI 131072
#define GS_WLO 163840
#define GSMEM  196608

__global__ void __launch_bounds__(512, 1)
k_gemm_mma(const float* __restrict__ x,
           const float* __restrict__ bq, const float* __restrict__ bk,
           const float* __restrict__ bv, const float* __restrict__ bs) {
    extern __shared__ char smem[];
    uint32_t sb = smem_u32(smem);
    const int t = threadIdx.x;
    const int w = t >> 5, lane = t & 31;
    const int wr = w >> 1;
    const int wc = w & 1;
    const int row0 = blockIdx.x * 256;
    const int which = blockIdx.y;

    load_x_tile(smem + GS_XHI, g_xhi + (size_t)row0 * DD, t);
    load_x_tile(smem + GS_XLO, g_xlo + (size_t)row0 * DD, t);
    load_w_tile(smem + GS_WHI, g_whi + (size_t)which * DD * DD, t);
    load_w_tile(smem + GS_WLO, g_wlo + (size_t)which * DD * DD, t);
    __syncthreads();

    const int sub = lane >> 3;
    const int a_row = 32 * wr + (lane & 7) + ((sub & 1) << 3);
    const int a_kc2 = sub >> 1;
    const int ar7 = a_row & 7;
    const uint32_t a_off0 = (uint32_t)(a_row * 256);
    const uint32_t a_off1 = (uint32_t)((a_row + 16) * 256);
    const int b_n = 64 * wc + (lane & 7) + ((sub >> 1) << 3);
    const int b_kc2 = sub & 1;
    const int bn7 = b_n & 7;
    const uint32_t b_off = (uint32_t)(b_n * 256);

    float acc[2][8][4];
#pragma unroll
    for (int i = 0; i < 2; i++)
#pragma unroll
        for (int j = 0; j < 8; j++)
#pragma unroll
            for (int q = 0; q < 4; q++) acc[i][j][q] = 0.f;

#pragma unroll
    for (int s = 0; s < 8; s++) {
        const uint32_t akc = ((uint32_t)((2 * s + a_kc2) ^ ar7)) << 4;
        const uint32_t bkc = ((uint32_t)((2 * s + b_kc2) ^ bn7)) << 4;
        uint32_t ah0[4], ah1[4], al0[4], al1[4];
        ldsm4(ah0[0], ah0[1], ah0[2], ah0[3], sb + GS_XHI + a_off0 + akc);
        ldsm4(ah1[0], ah1[1], ah1[2], ah1[3], sb + GS_XHI + a_off1 + akc);
        ldsm4(al0[0], al0[1], al0[2], al0[3], sb + GS_XLO + a_off0 + akc);
        ldsm4(al1[0], al1[1], al1[2], al1[3], sb + GS_XLO + a_off1 + akc);
#pragma unroll
        for (int p = 0; p < 4; p++) {
            const uint32_t poff = (uint32_t)(p * 4096);
            uint32_t r0, r1, r2, r3;
            ldsm4(r0, r1, r2, r3, sb + GS_WHI + b_off + poff + bkc);
            mma16816(acc[0][2 * p],     ah0, r0, r1);
            mma16816(acc[0][2 * p + 1], ah0, r2, r3);
            mma16816(acc[1][2 * p],     ah1, r0, r1);
            mma16816(acc[1][2 * p + 1], ah1, r2, r3);
            mma16816(acc[0][2 * p],     al0, r0, r1);
            mma16816(acc[0][2 * p + 1], al0, r2, r3);
            mma16816(acc[1][2 * p],     al1, r0, r1);
            mma16816(acc[1][2 * p + 1], al1, r2, r3);
            ldsm4(r0, r1, r2, r3, sb + GS_WLO + b_off + poff + bkc);
            mma16816(acc[0][2 * p],     ah0, r0, r1);
            mma16816(acc[0][2 * p + 1], ah0, r2, r3);
            mma16816(acc[1][2 * p],     ah1, r0, r1);
            mma16816(acc[1][2 * p + 1], ah1, r2, r3);
        }
    }

    float* out;
    const float* bias;
    switch (which) {
        case 0: out = g_q;    bias = bq; break;
        case 1: out = g_k;    bias = bk; break;
        case 2: out = g_v;    bias = bv; break;
        case 3: out = g_base; bias = bs; break;
        default: out = g_xw;  bias = 0;  break;
    }
    const int rbase = row0 + 32 * wr + (lane >> 2);
    const int colb = 64 * wc + (lane & 3) * 2;
#pragma unroll
    for (int rg = 0; rg < 2; rg++) {
        const int r0i = rbase + 16 * rg;
        const bool ok0 = r0i < NN, ok1 = (r0i + 8) < NN;
#pragma unroll
        for (int nt = 0; nt < 8; nt++) {
            int col = nt * 8 + colb;
            float bx = 0.f, by = 0.f;
            if (bias) { bx = __ldg(bias + col); by = __ldg(bias + col + 1); }
            float2 v0 = make_float2(acc[rg][nt][0] + bx, acc[rg][nt][1] + by);
            float2 v1 = make_float2(acc[rg][nt][2] + bx, acc[rg][nt][3] + by);
            if (which == 3) {
                if (ok0) {
                    float2 xv = *(const float2*)(x + (size_t)r0i * DD + col);
                    v0.x += xv.x; v0.y += xv.y;
                }
                if (ok1) {
                    float2 xv = *(const float2*)(x + (size_t)(r0i + 8) * DD + col);
                    v1.x += xv.x; v1.y += xv.y;
                }
            }
            if (ok0) *(float2*)(out + (size_t)r0i * DD + col) = v0;
            if (ok1) *(float2*)(out + (size_t)(r0i + 8) * DD + col) = v1;
        }
    }
}

// ---------------- K2: fused per-node attention + GCN + LN + ReLU ----------
// warp per node; lane covers channels [4*lane, 4*lane+3]; head = lane>>4.
// GCN accumulation merged into loop 1; chunk-0 ex kept in registers.
__global__ void __launch_bounds__(256)
k_fused(const float* __restrict__ bgcn,
        const float* __restrict__ gamma,
        const float* __restrict__ beta,
        float* __restrict__ out) {
    int i = blockIdx.x * 8 + (threadIdx.x >> 5);
    if (i >= NN) return;
    const int lane = threadIdx.x & 31;
    const int c4 = lane * 4;
    const int head = lane >> 4;

    const int off = g_off[i];
    const int deg = g_deg[i];
    const int end = off + deg;
    const float dis_i = g_dis[i];

    float4 qv = *(const float4*)(g_q + (size_t)i * DD + c4);

    float den = 0.f;
    float4 acc = make_float4(0.f, 0.f, 0.f, 0.f);
    float2 myex0 = make_float2(0.f, 0.f);
    int myidx0 = 0;

    // ---- loop 1: logits -> ex + den, and GCN (w * xw) accumulation ----
    for (int base = off; base < end; base += 32) {
        int cnt = min(32, end - base);
        int myidx = (lane < cnt) ? __ldg(g_es + base + lane) : 0;
        if (base == off) myidx0 = myidx;
        for (int j = 0; j < cnt; j++) {
            int src = __shfl_sync(0xffffffffu, myidx, j);
            float4 kv = *(const float4*)(g_k + (size_t)src * DD + c4);
            float4 xv = *(const float4*)(g_xw + (size_t)src * DD + c4);
            float s = qv.x * kv.x + qv.y * kv.y + qv.z * kv.z + qv.w * kv.w;
            s += __shfl_xor_sync(0xffffffffu, s, 8);
            s += __shfl_xor_sync(0xffffffffu, s, 4);
            s += __shfl_xor_sync(0xffffffffu, s, 2);
            s += __shfl_xor_sync(0xffffffffu, s, 1);
            float ex = __expf(s * 0.125f);   // / sqrt(64)
            den += ex;                        // per-lane copy of its head's den
            float w = g_dis[src] * dis_i;
            acc.x += w * xv.x; acc.y += w * xv.y;
            acc.z += w * xv.z; acc.w += w * xv.w;
            float e0 = __shfl_sync(0xffffffffu, ex, 0);
            float e1 = __shfl_sync(0xffffffffu, ex, 16);
            if (base == off) {
                if (lane == j) myex0 = make_float2(e0, e1);
            } else if (lane == 0) {
                *(float2*)(g_ex + (size_t)(base + j) * 2) = make_float2(e0, e1);
            }
        }
    }
    den += 1e-16f;
    float rden = 1.0f / den;

    // ---- loop 2: alpha-weighted V accumulation ----
    for (int base = off; base < end; base += 32) {
        int cnt = min(32, end - base);
        int myidx;
        float2 myex;
        if (base == off) {
            myidx = myidx0;
            myex = myex0;
        } else {
            myidx = (lane < cnt) ? __ldg(g_es + base + lane) : 0;
            myex = (lane < cnt) ? *(const float2*)(g_ex + (size_t)(base + lane) * 2)
                                : make_float2(0.f, 0.f);
        }
        for (int j = 0; j < cnt; j++) {
            int src = __shfl_sync(0xffffffffu, myidx, j);
            float e0 = __shfl_sync(0xffffffffu, myex.x, j);
            float e1 = __shfl_sync(0xffffffffu, myex.y, j);
            float alpha = (head ? e1 : e0) * rden;
            float4 vv = *(const float4*)(g_v + (size_t)src * DD + c4);
            acc.x += alpha * vv.x; acc.y += alpha * vv.y;
            acc.z += alpha * vv.z; acc.w += alpha * vv.w;
        }
    }

    // ---- finalize: base + self-loop + LayerNorm + ReLU ----
    float4 b = *(const float4*)(g_base + (size_t)i * DD + c4);
    float4 xv = *(const float4*)(g_xw + (size_t)i * DD + c4);
    float4 bg = *(const float4*)(bgcn + c4);
    float d2 = dis_i * dis_i;

    float v0 = b.x + acc.x + d2 * xv.x + bg.x;
    float v1 = b.y + acc.y + d2 * xv.y + bg.y;
    float v2 = b.z + acc.z + d2 * xv.z + bg.z;
    float v3 = b.w + acc.w + d2 * xv.w + bg.w;

    float s = v0 + v1 + v2 + v3;
#pragma unroll
    for (int o = 16; o > 0; o >>= 1) s += __shfl_xor_sync(0xffffffffu, s, o);
    float mu = s * (1.0f / 128.0f);

    float d0 = v0 - mu, d1 = v1 - mu, d2_ = v2 - mu, d3 = v3 - mu;
    float sq = d0 * d0 + d1 * d1 + d2_ * d2_ + d3 * d3;
#pragma unroll
    for (int o = 16; o > 0; o >>= 1) sq += __shfl_xor_sync(0xffffffffu, sq, o);
    float inv = rsqrtf(sq * (1.0f / 128.0f) + 1e-5f);

    float4 g = *(const float4*)(gamma + c4);
    float4 be = *(const float4*)(beta + c4);
    float4 o4;
    o4.x = fmaxf(d0 * inv * g.x + be.x, 0.0f);
    o4.y = fmaxf(d1 * inv * g.y + be.y, 0.0f);
    o4.z = fmaxf(d2_ * inv * g.z + be.z, 0.0f);
    o4.w = fmaxf(d3 * inv * g.w + be.w, 0.0f);
    *(float4*)(out + (size_t)i * DD + c4) = o4;
}

// ---------------- launch ----------------
extern "C" void kernel_launch(void* const* d_in, const int* in_sizes, int n_in,
                              void* d_out, int out_size) {
    const float* x     = (const float*)d_in[0];
    const int*   ei    = (const int*)d_in[1];
    const float* Wq    = (const float*)d_in[2];
    const float* bq    = (const float*)d_in[3];
    const float* Wk    = (const float*)d_in[4];
    const float* bk    = (const float*)d_in[5];
    const float* Wv    = (const float*)d_in[6];
    const float* bv    = (const float*)d_in[7];
    const float* Wskip = (const float*)d_in[8];
    const float* bskip = (const float*)d_in[9];
    const float* Wgcn  = (const float*)d_in[10];
    const float* bgcn  = (const float*)d_in[11];
    const float* gamma = (const float*)d_in[12];
    const float* beta  = (const float*)d_in[13];
    float* out = (float*)d_out;

    static int smem_set = 0;
    if (!smem_set) {
        cudaFuncSetAttribute(k_gemm_mma,
                             cudaFuncAttributeMaxDynamicSharedMemorySize, GSMEM);
        smem_set = 1;
    }

    k_init<<<(NN + 255) / 256, 256>>>();
    k_prep_x<<<(NP * DD / 4 + 255) / 256, 256>>>(x);
    k_prep_w<<<(5 * DD * DD + 255) / 256, 256>>>(Wq, Wk, Wv, Wskip, Wgcn);
    k_deg<<<(EE + 255) / 256, 256>>>(ei);
    k_node<<<(NN + 255) / 256, 256>>>();
    k_scatter<<<(EE + 255) / 256, 256>>>(ei);
    dim3 ggrid(NRB, 5);
    k_gemm_mma<<<ggrid, 512, GSMEM>>>(x, bq, bk, bv, bskip);
    k_fused<<<(NN + 7) / 8, 256>>>(bgcn, gamma, beta, out);
}

// round 13
// speedup vs baseline: 1.0303x; 1.0299x over previous
#include <cuda_runtime.h>
#include <cuda_bf16.h>
#include <cstdint>
#include <math.h>

#define NN 100000
#define NP 100096   /* 391 * 256 */
#define DD 128
#define HH 2
#define EE 640000
#define NRB 391     /* row blocks of 256 */

// ---------------- scratch (device globals; no runtime allocation) ----------
__device__ float g_q[NP * DD];
__device__ float g_k[NP * DD];
__device__ float g_v[NP * DD];
__device__ float g_xw[NP * DD];
__device__ float g_base[NP * DD];
__device__ float g_ex[EE * HH];   // (ex_h0, ex_h1) per dst-sorted edge
__device__ float g_dis[NN];
__device__ int   g_deg[NN];
__device__ int   g_off[NN];
__device__ int   g_cur[NN];
__device__ int   g_es[EE];        // dst-sorted src indices
__device__ int   g_ctr;
__device__ __align__(16) __nv_bfloat16 g_xhi[NP * DD];
__device__ __align__(16) __nv_bfloat16 g_xlo[NP * DD];
__device__ __align__(16) __nv_bfloat16 g_whi[5 * DD * DD];  // transposed [which][n][k]
__device__ __align__(16) __nv_bfloat16 g_wlo[5 * DD * DD];

// ---------------- helpers ----------------
__device__ __forceinline__ uint32_t smem_u32(const void* p) {
    uint32_t a;
    asm("{ .reg .u64 t; cvta.to.shared.u64 t, %1; cvt.u32.u64 %0, t; }"
        : "=r"(a) : "l"(p));
    return a;
}
__device__ __forceinline__ void ldsm4(uint32_t& r0, uint32_t& r1, uint32_t& r2,
                                      uint32_t& r3, uint32_t addr) {
    asm volatile("ldmatrix.sync.aligned.m8n8.x4.shared.b16 {%0,%1,%2,%3}, [%4];"
                 : "=r"(r0), "=r"(r1), "=r"(r2), "=r"(r3) : "r"(addr));
}
__device__ __forceinline__ void mma16816(float* c, const uint32_t* a,
                                         uint32_t b0, uint32_t b1) {
    asm volatile(
        "mma.sync.aligned.m16n8k16.row.col.f32.bf16.bf16.f32 "
        "{%0,%1,%2,%3}, {%4,%5,%6,%7}, {%8,%9}, {%0,%1,%2,%3};"
        : "+f"(c[0]), "+f"(c[1]), "+f"(c[2]), "+f"(c[3])
        : "r"(a[0]), "r"(a[1]), "r"(a[2]), "r"(a[3]), "r"(b0), "r"(b1));
}

// ---------------- K0: init scratch ----------------
__global__ void k_init() {
    int i = blockIdx.x * blockDim.x + threadIdx.x;
    if (i < NN) { g_deg[i] = 0; g_cur[i] = 0; }
    if (i == 0) g_ctr = 0;
}

// ---------------- K_deg: degree count ----------------
__global__ void k_deg(const int* __restrict__ ei) {
    int e = blockIdx.x * blockDim.x + threadIdx.x;
    if (e >= EE) return;
    atomicAdd(&g_deg[__ldg(ei + EE + e)], 1);
}

// ---------------- K_node: offsets (warp-aggregated alloc) + dis ----------
__global__ void k_node() {
    int i = blockIdx.x * blockDim.x + threadIdx.x;
    int lane = threadIdx.x & 31;
    int d = (i < NN) ? g_deg[i] : 0;
    int incl = d;
#pragma unroll
    for (int o = 1; o < 32; o <<= 1) {
        int n = __shfl_up_sync(0xffffffffu, incl, o);
        if (lane >= o) incl += n;
    }
    int base = 0;
    if (lane == 31) base = atomicAdd(&g_ctr, incl);
    base = __shfl_sync(0xffffffffu, base, 31);
    if (i < NN) {
        g_off[i] = base + incl - d;
        g_dis[i] = rsqrtf((float)d + 1.0f);
    }
}

// ---------------- K_scatter: build dst-sorted src list ----------------
__global__ void k_scatter(const int* __restrict__ ei) {
    int e = blockIdx.x * blockDim.x + threadIdx.x;
    if (e >= EE) return;
    int dst = __ldg(ei + EE + e);
    int pos = g_off[dst] + atomicAdd(&g_cur[dst], 1);
    g_es[pos] = __ldg(ei + e);
}

// ---------------- K_prep: hi/lo bf16 split of x (padded) ----------------
__global__ void k_prep_x(const float* __restrict__ x) {
    int i = blockIdx.x * blockDim.x + threadIdx.x;  // per 4 elems
    if (i >= NP * DD / 4) return;
    float4 v = make_float4(0.f, 0.f, 0.f, 0.f);
    if (i < NN * DD / 4) v = ((const float4*)x)[i];
    float a[4] = {v.x, v.y, v.z, v.w};
    unsigned short h[4], l[4];
#pragma unroll
    for (int j = 0; j < 4; j++) {
        __nv_bfloat16 hb = __float2bfloat16(a[j]);
        __nv_bfloat16 lb = __float2bfloat16(a[j] - __bfloat162float(hb));
        h[j] = __bfloat16_as_ushort(hb);
        l[j] = __bfloat16_as_ushort(lb);
    }
    ((ushort4*)g_xhi)[i] = make_ushort4(h[0], h[1], h[2], h[3]);
    ((ushort4*)g_xlo)[i] = make_ushort4(l[0], l[1], l[2], l[3]);
}

// ---------------- K_prep: transpose + hi/lo split of the 5 weights -------
__global__ void k_prep_w(const float* __restrict__ Wq, const float* __restrict__ Wk,
                         const float* __restrict__ Wv, const float* __restrict__ Ws,
                         const float* __restrict__ Wg) {
    int i = blockIdx.x * blockDim.x + threadIdx.x;
    if (i >= 5 * DD * DD) return;
    int which = i >> 14;
    int r = i & 16383;
    int n = r >> 7, k = r & 127;
    const float* W;
    switch (which) {
        case 0: W = Wq; break; case 1: W = Wk; break; case 2: W = Wv; break;
        case 3: W = Ws; break; default: W = Wg; break;
    }
    float v = W[k * DD + n];  // transposed: Wt[n][k] = W[k][n]
    __nv_bfloat16 hb = __float2bfloat16(v);
    __nv_bfloat16 lb = __float2bfloat16(v - __bfloat162float(hb));
    g_whi[i] = hb;
    g_wlo[i] = lb;
}

// ---------------- swizzled tile loaders (512 threads) ---------------------
__device__ __forceinline__ void load_x_tile(char* dst, const __nv_bfloat16* src, int t) {
#pragma unroll
    for (int i = 0; i < 8; i++) {
        int idx = i * 512 + t;
        int row = idx >> 4;
        int kc = idx & 15;
        uint32_t off = (uint32_t)(row * 256 + ((kc ^ (row & 7)) << 4));
        *(uint4*)(dst + off) = *(const uint4*)((const char*)src + row * 256 + kc * 16);
    }
}
__device__ __forceinline__ void load_w_tile(char* dst, const __nv_bfloat16* src, int t) {
#pragma unroll
    for (int i = 0; i < 4; i++) {
        int idx = i * 512 + t;
        int row = idx >> 4;
        int kc = idx & 15;
        uint32_t off = (uint32_t)(row * 256 + ((kc ^ (row & 7)) << 4));
        *(uint4*)(dst + off) = *(const uint4*)((const char*)src + row * 256 + kc * 16);
    }
}

// ---------------- K1: mma.sync GEMM, one weight per block (R8, unchanged) -
#define GS_XHI 0
#define GS_XLO 65536
#define GS_WHI 131072
#define GS_WLO 163840
#define GSMEM  196608

__global__ void __launch_bounds__(512, 1)
k_gemm_mma(const float* __restrict__ x,
           const float* __restrict__ bq, const float* __restrict__ bk,
           const float* __restrict__ bv, const float* __restrict__ bs) {
    extern __shared__ char smem[];
    uint32_t sb = smem_u32(smem);
    const int t = threadIdx.x;
    const int w = t >> 5, lane = t & 31;
    const int wr = w >> 1;
    const int wc = w & 1;
    const int row0 = blockIdx.x * 256;
    const int which = blockIdx.y;

    load_x_tile(smem + GS_XHI, g_xhi + (size_t)row0 * DD, t);
    load_x_tile(smem + GS_XLO, g_xlo + (size_t)row0 * DD, t);
    load_w_tile(smem + GS_WHI, g_whi + (size_t)which * DD * DD, t);
    load_w_tile(smem + GS_WLO, g_wlo + (size_t)which * DD * DD, t);
    __syncthreads();

    const int sub = lane >> 3;
    const int a_row = 32 * wr + (lane & 7) + ((sub & 1) << 3);
    const int a_kc2 = sub >> 1;
    const int ar7 = a_row & 7;
    const uint32_t a_off0 = (uint32_t)(a_row * 256);
    const uint32_t a_off1 = (uint32_t)((a_row + 16) * 256);
    const int b_n = 64 * wc + (lane & 7) + ((sub >> 1) << 3);
    const int b_kc2 = sub & 1;
    const int bn7 = b_n & 7;
    const uint32_t b_off = (uint32_t)(b_n * 256);

    float acc[2][8][4];
#pragma unroll
    for (int i = 0; i < 2; i++)
#pragma unroll
        for (int j = 0; j < 8; j++)
#pragma unroll
            for (int q = 0; q < 4; q++) acc[i][j][q] = 0.f;

#pragma unroll
    for (int s = 0; s < 8; s++) {
        const uint32_t akc = ((uint32_t)((2 * s + a_kc2) ^ ar7)) << 4;
        const uint32_t bkc = ((uint32_t)((2 * s + b_kc2) ^ bn7)) << 4;
        uint32_t ah0[4], ah1[4], al0[4], al1[4];
        ldsm4(ah0[0], ah0[1], ah0[2], ah0[3], sb + GS_XHI + a_off0 + akc);
        ldsm4(ah1[0], ah1[1], ah1[2], ah1[3], sb + GS_XHI + a_off1 + akc);
        ldsm4(al0[0], al0[1], al0[2], al0[3], sb + GS_XLO + a_off0 + akc);
        ldsm4(al1[0], al1[1], al1[2], al1[3], sb + GS_XLO + a_off1 + akc);
#pragma unroll
        for (int p = 0; p < 4; p++) {
            const uint32_t poff = (uint32_t)(p * 4096);
            uint32_t r0, r1, r2, r3;
            ldsm4(r0, r1, r2, r3, sb + GS_WHI + b_off + poff + bkc);
            mma16816(acc[0][2 * p],     ah0, r0, r1);
            mma16816(acc[0][2 * p + 1], ah0, r2, r3);
            mma16816(acc[1][2 * p],     ah1, r0, r1);
            mma16816(acc[1][2 * p + 1], ah1, r2, r3);
            mma16816(acc[0][2 * p],     al0, r0, r1);
            mma16816(acc[0][2 * p + 1], al0, r2, r3);
            mma16816(acc[1][2 * p],     al1, r0, r1);
            mma16816(acc[1][2 * p + 1], al1, r2, r3);
            ldsm4(r0, r1, r2, r3, sb + GS_WLO + b_off + poff + bkc);
            mma16816(acc[0][2 * p],     ah0, r0, r1);
            mma16816(acc[0][2 * p + 1], ah0, r2, r3);
            mma16816(acc[1][2 * p],     ah1, r0, r1);
            mma16816(acc[1][2 * p + 1], ah1, r2, r3);
        }
    }

    float* out;
    const float* bias;
    switch (which) {
        case 0: out = g_q;    bias = bq; break;
        case 1: out = g_k;    bias = bk; break;
        case 2: out = g_v;    bias = bv; break;
        case 3: out = g_base; bias = bs; break;
        default: out = g_xw;  bias = 0;  break;
    }
    const int rbase = row0 + 32 * wr + (lane >> 2);
    const int colb = 64 * wc + (lane & 3) * 2;
#pragma unroll
    for (int rg = 0; rg < 2; rg++) {
        const int r0i = rbase + 16 * rg;
        const bool ok0 = r0i < NN, ok1 = (r0i + 8) < NN;
#pragma unroll
        for (int nt = 0; nt < 8; nt++) {
            int col = nt * 8 + colb;
            float bx = 0.f, by = 0.f;
            if (bias) { bx = __ldg(bias + col); by = __ldg(bias + col + 1); }
            float2 v0 = make_float2(acc[rg][nt][0] + bx, acc[rg][nt][1] + by);
            float2 v1 = make_float2(acc[rg][nt][2] + bx, acc[rg][nt][3] + by);
            if (which == 3) {
                if (ok0) {
                    float2 xv = *(const float2*)(x + (size_t)r0i * DD + col);
                    v0.x += xv.x; v0.y += xv.y;
                }
                if (ok1) {
                    float2 xv = *(const float2*)(x + (size_t)(r0i + 8) * DD + col);
                    v1.x += xv.x; v1.y += xv.y;
                }
            }
            if (ok0) *(float2*)(out + (size_t)r0i * DD + col) = v0;
            if (ok1) *(float2*)(out + (size_t)(r0i + 8) * DD + col) = v1;
        }
    }
}

// ---------------- K2: fused per-node attention + GCN + LN + ReLU ----------
// R9 structure, inner edge loops unrolled by 2 with interleaved chains.
// g_ex stores are float2 (8B-aligned); float4 would fault on odd offsets.
__global__ void __launch_bounds__(256)
k_fused(const float* __restrict__ bgcn,
        const float* __restrict__ gamma,
        const float* __restrict__ beta,
        float* __restrict__ out) {
    int i = blockIdx.x * 8 + (threadIdx.x >> 5);
    if (i >= NN) return;
    const int lane = threadIdx.x & 31;
    const int c4 = lane * 4;
    const int head = lane >> 4;

    const int off = g_off[i];
    const int deg = g_deg[i];
    const int end = off + deg;
    const float dis_i = g_dis[i];

    float4 qv = *(const float4*)(g_q + (size_t)i * DD + c4);

    // ---- loop 1: logits -> ex, per-lane denominator (2 edges/iter) ----
    float den = 0.f;
    for (int base = off; base < end; base += 32) {
        int cnt = min(32, end - base);
        int myidx = (lane < cnt) ? __ldg(g_es + base + lane) : 0;
        int j = 0;
        for (; j + 2 <= cnt; j += 2) {
            int src0 = __shfl_sync(0xffffffffu, myidx, j);
            int src1 = __shfl_sync(0xffffffffu, myidx, j + 1);
            float4 k0 = *(const float4*)(g_k + (size_t)src0 * DD + c4);
            float4 k1 = *(const float4*)(g_k + (size_t)src1 * DD + c4);
            float s0 = qv.x * k0.x + qv.y * k0.y + qv.z * k0.z + qv.w * k0.w;
            float s1 = qv.x * k1.x + qv.y * k1.y + qv.z * k1.z + qv.w * k1.w;
#pragma unroll
            for (int o = 8; o > 0; o >>= 1) {
                s0 += __shfl_xor_sync(0xffffffffu, s0, o);
                s1 += __shfl_xor_sync(0xffffffffu, s1, o);
            }
            float ex0 = __expf(s0 * 0.125f);
            float ex1 = __expf(s1 * 0.125f);
            den += ex0 + ex1;
            float ex0h = __shfl_sync(0xffffffffu, ex0, 16);
            float ex1h = __shfl_sync(0xffffffffu, ex1, 16);
            if (lane == 0) {
                *(float2*)(g_ex + (size_t)(base + j) * 2) = make_float2(ex0, ex0h);
                *(float2*)(g_ex + (size_t)(base + j + 1) * 2) = make_float2(ex1, ex1h);
            }
        }
        if (j < cnt) {
            int src = __shfl_sync(0xffffffffu, myidx, j);
            float4 kv = *(const float4*)(g_k + (size_t)src * DD + c4);
            float s = qv.x * kv.x + qv.y * kv.y + qv.z * kv.z + qv.w * kv.w;
#pragma unroll
            for (int o = 8; o > 0; o >>= 1)
                s += __shfl_xor_sync(0xffffffffu, s, o);
            float ex = __expf(s * 0.125f);
            den += ex;
            float exh = __shfl_sync(0xffffffffu, ex, 16);
            if (lane == 0)
                *(float2*)(g_ex + (size_t)(base + j) * 2) = make_float2(ex, exh);
        }
    }
    den += 1e-16f;
    float rden = 1.0f / den;

    // ---- loop 2: alpha-weighted V + norm-weighted XW (2 edges/iter) ----
    float4 acc = make_float4(0.f, 0.f, 0.f, 0.f);
    for (int base = off; base < end; base += 32) {
        int cnt = min(32, end - base);
        int myidx = 0;
        float2 myex = make_float2(0.f, 0.f);
        if (lane < cnt) {
            myidx = __ldg(g_es + base + lane);
            myex = *(const float2*)(g_ex + (size_t)(base + lane) * 2);
        }
        int j = 0;
        for (; j + 2 <= cnt; j += 2) {
            int src0 = __shfl_sync(0xffffffffu, myidx, j);
            int src1 = __shfl_sync(0xffffffffu, myidx, j + 1);
            float e00 = __shfl_sync(0xffffffffu, myex.x, j);
            float e01 = __shfl_sync(0xffffffffu, myex.y, j);
            float e10 = __shfl_sync(0xffffffffu, myex.x, j + 1);
            float e11 = __shfl_sync(0xffffffffu, myex.y, j + 1);
            float4 v0 = *(const float4*)(g_v + (size_t)src0 * DD + c4);
            float4 x0 = *(const float4*)(g_xw + (size_t)src0 * DD + c4);
            float4 v1 = *(const float4*)(g_v + (size_t)src1 * DD + c4);
            float4 x1 = *(const float4*)(g_xw + (size_t)src1 * DD + c4);
            float alpha0 = (head ? e01 : e00) * rden;
            float alpha1 = (head ? e11 : e10) * rden;
            float w0 = g_dis[src0] * dis_i;
            float w1 = g_dis[src1] * dis_i;
            acc.x += alpha0 * v0.x + w0 * x0.x + alpha1 * v1.x + w1 * x1.x;
            acc.y += alpha0 * v0.y + w0 * x0.y + alpha1 * v1.y + w1 * x1.y;
            acc.z += alpha0 * v0.z + w0 * x0.z + alpha1 * v1.z + w1 * x1.z;
            acc.w += alpha0 * v0.w + w0 * x0.w + alpha1 * v1.w + w1 * x1.w;
        }
        if (j < cnt) {
            int src = __shfl_sync(0xffffffffu, myidx, j);
            float e0 = __shfl_sync(0xffffffffu, myex.x, j);
            float e1 = __shfl_sync(0xffffffffu, myex.y, j);
            float alpha = (head ? e1 : e0) * rden;
            float w = g_dis[src] * dis_i;
            float4 vv = *(const float4*)(g_v + (size_t)src * DD + c4);
            float4 xv = *(const float4*)(g_xw + (size_t)src * DD + c4);
            acc.x += alpha * vv.x + w * xv.x;
            acc.y += alpha * vv.y + w * xv.y;
            acc.z += alpha * vv.z + w * xv.z;
            acc.w += alpha * vv.w + w * xv.w;
        }
    }

    // ---- finalize: base + self-loop + LayerNorm + ReLU ----
    float4 b = *(const float4*)(g_base + (size_t)i * DD + c4);
    float4 xv = *(const float4*)(g_xw + (size_t)i * DD + c4);
    float4 bg = *(const float4*)(bgcn + c4);
    float d2 = dis_i * dis_i;

    float v0 = b.x + acc.x + d2 * xv.x + bg.x;
    float v1 = b.y + acc.y + d2 * xv.y + bg.y;
    float v2 = b.z + acc.z + d2 * xv.z + bg.z;
    float v3 = b.w + acc.w + d2 * xv.w + bg.w;

    float s = v0 + v1 + v2 + v3;
#pragma unroll
    for (int o = 16; o > 0; o >>= 1) s += __shfl_xor_sync(0xffffffffu, s, o);
    float mu = s * (1.0f / 128.0f);

    float d0 = v0 - mu, d1 = v1 - mu, d2_ = v2 - mu, d3 = v3 - mu;
    float sq = d0 * d0 + d1 * d1 + d2_ * d2_ + d3 * d3;
#pragma unroll
    for (int o = 16; o > 0; o >>= 1) sq += __shfl_xor_sync(0xffffffffu, sq, o);
    float inv = rsqrtf(sq * (1.0f / 128.0f) + 1e-5f);

    float4 g = *(const float4*)(gamma + c4);
    float4 be = *(const float4*)(beta + c4);
    float4 o4;
    o4.x = fmaxf(d0 * inv * g.x + be.x, 0.0f);
    o4.y = fmaxf(d1 * inv * g.y + be.y, 0.0f);
    o4.z = fmaxf(d2_ * inv * g.z + be.z, 0.0f);
    o4.w = fmaxf(d3 * inv * g.w + be.w, 0.0f);
    *(float4*)(out + (size_t)i * DD + c4) = o4;
}

// ---------------- launch ----------------
extern "C" void kernel_launch(void* const* d_in, const int* in_sizes, int n_in,
                              void* d_out, int out_size) {
    const float* x     = (const float*)d_in[0];
    const int*   ei    = (const int*)d_in[1];
    const float* Wq    = (const float*)d_in[2];
    const float* bq    = (const float*)d_in[3];
    const float* Wk    = (const float*)d_in[4];
    const float* bk    = (const float*)d_in[5];
    const float* Wv    = (const float*)d_in[6];
    const float* bv    = (const float*)d_in[7];
    const float* Wskip = (const float*)d_in[8];
    const float* bskip = (const float*)d_in[9];
    const float* Wgcn  = (const float*)d_in[10];
    const float* bgcn  = (const float*)d_in[11];
    const float* gamma = (const float*)d_in[12];
    const float* beta  = (const float*)d_in[13];
    float* out = (float*)d_out;

    static int smem_set = 0;
    if (!smem_set) {
        cudaFuncSetAttribute(k_gemm_mma,
                             cudaFuncAttributeMaxDynamicSharedMemorySize, GSMEM);
        smem_set = 1;
    }

    k_init<<<(NN + 255) / 256, 256>>>();
    k_prep_x<<<(NP * DD / 4 + 255) / 256, 256>>>(x);
    k_prep_w<<<(5 * DD * DD + 255) / 256, 256>>>(Wq, Wk, Wv, Wskip, Wgcn);
    k_deg<<<(EE + 255) / 256, 256>>>(ei);
    k_node<<<(NN + 255) / 256, 256>>>();
    k_scatter<<<(EE + 255) / 256, 256>>>(ei);
    dim3 ggrid(NRB, 5);
    k_gemm_mma<<<ggrid, 512, GSMEM>>>(x, bq, bk, bv, bskip);
    k_fused<<<(NN + 7) / 8, 256>>>(bgcn, gamma, beta, out);
}

// round 14
// speedup vs baseline: 1.0530x; 1.0220x over previous
#include <cuda_runtime.h>
#include <cuda_bf16.h>
#include <cstdint>
#include <math.h>

#define NN 100000
#define NP 100096   /* 391 * 256 */
#define DD 128
#define HH 2
#define EE 640000
#define NRB 391     /* row blocks of 256 */

// ---------------- scratch (device globals; no runtime allocation) ----------
__device__ float g_q[NP * DD];
__device__ float g_k[NP * DD];
__device__ float g_v[NP * DD];
__device__ float g_xw[NP * DD];
__device__ float g_base[NP * DD];
__device__ float g_ex[EE * HH];   // (ex_h0, ex_h1) per dst-sorted edge
__device__ float g_dis[NN];
__device__ int   g_deg[NN];
__device__ int   g_off[NN];
__device__ int   g_cur[NN];
__device__ int   g_es[EE];        // dst-sorted src indices
__device__ int   g_ctr;
__device__ __align__(16) __nv_bfloat16 g_xhi[NP * DD];
__device__ __align__(16) __nv_bfloat16 g_xlo[NP * DD];
__device__ __align__(16) __nv_bfloat16 g_whi[5 * DD * DD];  // transposed [which][n][k]
__device__ __align__(16) __nv_bfloat16 g_wlo[5 * DD * DD];

// ---------------- helpers ----------------
__device__ __forceinline__ uint32_t smem_u32(const void* p) {
    uint32_t a;
    asm("{ .reg .u64 t; cvta.to.shared.u64 t, %1; cvt.u32.u64 %0, t; }"
        : "=r"(a) : "l"(p));
    return a;
}
__device__ __forceinline__ void ldsm4(uint32_t& r0, uint32_t& r1, uint32_t& r2,
                                      uint32_t& r3, uint32_t addr) {
    asm volatile("ldmatrix.sync.aligned.m8n8.x4.shared.b16 {%0,%1,%2,%3}, [%4];"
                 : "=r"(r0), "=r"(r1), "=r"(r2), "=r"(r3) : "r"(addr));
}
__device__ __forceinline__ void mma16816(float* c, const uint32_t* a,
                                         uint32_t b0, uint32_t b1) {
    asm volatile(
        "mma.sync.aligned.m16n8k16.row.col.f32.bf16.bf16.f32 "
        "{%0,%1,%2,%3}, {%4,%5,%6,%7}, {%8,%9}, {%0,%1,%2,%3};"
        : "+f"(c[0]), "+f"(c[1]), "+f"(c[2]), "+f"(c[3])
        : "r"(a[0]), "r"(a[1]), "r"(a[2]), "r"(a[3]), "r"(b0), "r"(b1));
}

// ---------------- K0: init scratch ----------------
__global__ void k_init() {
    int i = blockIdx.x * blockDim.x + threadIdx.x;
    if (i < NN) { g_deg[i] = 0; g_cur[i] = 0; }
    if (i == 0) g_ctr = 0;
}

// ---------------- K_deg: degree count ----------------
__global__ void k_deg(const int* __restrict__ ei) {
    int e = blockIdx.x * blockDim.x + threadIdx.x;
    if (e >= EE) return;
    atomicAdd(&g_deg[__ldg(ei + EE + e)], 1);
}

// ---------------- K_node: offsets (warp-aggregated alloc) + dis ----------
__global__ void k_node() {
    int i = blockIdx.x * blockDim.x + threadIdx.x;
    int lane = threadIdx.x & 31;
    int d = (i < NN) ? g_deg[i] : 0;
    int incl = d;
#pragma unroll
    for (int o = 1; o < 32; o <<= 1) {
        int n = __shfl_up_sync(0xffffffffu, incl, o);
        if (lane >= o) incl += n;
    }
    int base = 0;
    if (lane == 31) base = atomicAdd(&g_ctr, incl);
    base = __shfl_sync(0xffffffffu, base, 31);
    if (i < NN) {
        g_off[i] = base + incl - d;
        g_dis[i] = rsqrtf((float)d + 1.0f);
    }
}

// ---------------- K_scatter: build dst-sorted src list ----------------
__global__ void k_scatter(const int* __restrict__ ei) {
    int e = blockIdx.x * blockDim.x + threadIdx.x;
    if (e >= EE) return;
    int dst = __ldg(ei + EE + e);
    int pos = g_off[dst] + atomicAdd(&g_cur[dst], 1);
    g_es[pos] = __ldg(ei + e);
}

// ---------------- K_prep: hi/lo bf16 split of x (padded) ----------------
__global__ void k_prep_x(const float* __restrict__ x) {
    int i = blockIdx.x * blockDim.x + threadIdx.x;  // per 4 elems
    if (i >= NP * DD / 4) return;
    float4 v = make_float4(0.f, 0.f, 0.f, 0.f);
    if (i < NN * DD / 4) v = ((const float4*)x)[i];
    float a[4] = {v.x, v.y, v.z, v.w};
    unsigned short h[4], l[4];
#pragma unroll
    for (int j = 0; j < 4; j++) {
        __nv_bfloat16 hb = __float2bfloat16(a[j]);
        __nv_bfloat16 lb = __float2bfloat16(a[j] - __bfloat162float(hb));
        h[j] = __bfloat16_as_ushort(hb);
        l[j] = __bfloat16_as_ushort(lb);
    }
    ((ushort4*)g_xhi)[i] = make_ushort4(h[0], h[1], h[2], h[3]);
    ((ushort4*)g_xlo)[i] = make_ushort4(l[0], l[1], l[2], l[3]);
}

// ---------------- K_prep: transpose + hi/lo split of the 5 weights -------
__global__ void k_prep_w(const float* __restrict__ Wq, const float* __restrict__ Wk,
                         const float* __restrict__ Wv, const float* __restrict__ Ws,
                         const float* __restrict__ Wg) {
    int i = blockIdx.x * blockDim.x + threadIdx.x;
    if (i >= 5 * DD * DD) return;
    int which = i >> 14;
    int r = i & 16383;
    int n = r >> 7, k = r & 127;
    const float* W;
    switch (which) {
        case 0: W = Wq; break; case 1: W = Wk; break; case 2: W = Wv; break;
        case 3: W = Ws; break; default: W = Wg; break;
    }
    float v = W[k * DD + n];  // transposed: Wt[n][k] = W[k][n]
    __nv_bfloat16 hb = __float2bfloat16(v);
    __nv_bfloat16 lb = __float2bfloat16(v - __bfloat162float(hb));
    g_whi[i] = hb;
    g_wlo[i] = lb;
}

// ---------------- swizzled tile loaders (512 threads) ---------------------
__device__ __forceinline__ void load_x_tile(char* dst, const __nv_bfloat16* src, int t) {
#pragma unroll
    for (int i = 0; i < 8; i++) {
        int idx = i * 512 + t;
        int row = idx >> 4;
        int kc = idx & 15;
        uint32_t off = (uint32_t)(row * 256 + ((kc ^ (row & 7)) << 4));
        *(uint4*)(dst + off) = *(const uint4*)((const char*)src + row * 256 + kc * 16);
    }
}
__device__ __forceinline__ void load_w_tile(char* dst, const __nv_bfloat16* src, int t) {
#pragma unroll
    for (int i = 0; i < 4; i++) {
        int idx = i * 512 + t;
        int row = idx >> 4;
        int kc = idx & 15;
        uint32_t off = (uint32_t)(row * 256 + ((kc ^ (row & 7)) << 4));
        *(uint4*)(dst + off) = *(const uint4*)((const char*)src + row * 256 + kc * 16);
    }
}

// ---------------- K1: mma.sync GEMM, one weight per block (R8, unchanged) -
#define GS_XHI 0
#define GS_XLO 65536
#define GS_WHI 131072
#define GS_WLO 163840
#define GSMEM  196608

__global__ void __launch_bounds__(512, 1)
k_gemm_mma(const float* __restrict__ x,
           const float* __restrict__ bq, const float* __restrict__ bk,
           const float* __restrict__ bv, const float* __restrict__ bs) {
    extern __shared__ char smem[];
    uint32_t sb = smem_u32(smem);
    const int t = threadIdx.x;
    const int w = t >> 5, lane = t & 31;
    const int wr = w >> 1;
    const int wc = w & 1;
    const int row0 = blockIdx.x * 256;
    const int which = blockIdx.y;

    load_x_tile(smem + GS_XHI, g_xhi + (size_t)row0 * DD, t);
    load_x_tile(smem + GS_XLO, g_xlo + (size_t)row0 * DD, t);
    load_w_tile(smem + GS_WHI, g_whi + (size_t)which * DD * DD, t);
    load_w_tile(smem + GS_WLO, g_wlo + (size_t)which * DD * DD, t);
    __syncthreads();

    const int sub = lane >> 3;
    const int a_row = 32 * wr + (lane & 7) + ((sub & 1) << 3);
    const int a_kc2 = sub >> 1;
    const int ar7 = a_row & 7;
    const uint32_t a_off0 = (uint32_t)(a_row * 256);
    const uint32_t a_off1 = (uint32_t)((a_row + 16) * 256);
    const int b_n = 64 * wc + (lane & 7) + ((sub >> 1) << 3);
    const int b_kc2 = sub & 1;
    const int bn7 = b_n & 7;
    const uint32_t b_off = (uint32_t)(b_n * 256);

    float acc[2][8][4];
#pragma unroll
    for (int i = 0; i < 2; i++)
#pragma unroll
        for (int j = 0; j < 8; j++)
#pragma unroll
            for (int q = 0; q < 4; q++) acc[i][j][q] = 0.f;

#pragma unroll
    for (int s = 0; s < 8; s++) {
        const uint32_t akc = ((uint32_t)((2 * s + a_kc2) ^ ar7)) << 4;
        const uint32_t bkc = ((uint32_t)((2 * s + b_kc2) ^ bn7)) << 4;
        uint32_t ah0[4], ah1[4], al0[4], al1[4];
        ldsm4(ah0[0], ah0[1], ah0[2], ah0[3], sb + GS_XHI + a_off0 + akc);
        ldsm4(ah1[0], ah1[1], ah1[2], ah1[3], sb + GS_XHI + a_off1 + akc);
        ldsm4(al0[0], al0[1], al0[2], al0[3], sb + GS_XLO + a_off0 + akc);
        ldsm4(al1[0], al1[1], al1[2], al1[3], sb + GS_XLO + a_off1 + akc);
#pragma unroll
        for (int p = 0; p < 4; p++) {
            const uint32_t poff = (uint32_t)(p * 4096);
            uint32_t r0, r1, r2, r3;
            ldsm4(r0, r1, r2, r3, sb + GS_WHI + b_off + poff + bkc);
            mma16816(acc[0][2 * p],     ah0, r0, r1);
            mma16816(acc[0][2 * p + 1], ah0, r2, r3);
            mma16816(acc[1][2 * p],     ah1, r0, r1);
            mma16816(acc[1][2 * p + 1], ah1, r2, r3);
            mma16816(acc[0][2 * p],     al0, r0, r1);
            mma16816(acc[0][2 * p + 1], al0, r2, r3);
            mma16816(acc[1][2 * p],     al1, r0, r1);
            mma16816(acc[1][2 * p + 1], al1, r2, r3);
            ldsm4(r0, r1, r2, r3, sb + GS_WLO + b_off + poff + bkc);
            mma16816(acc[0][2 * p],     ah0, r0, r1);
            mma16816(acc[0][2 * p + 1], ah0, r2, r3);
            mma16816(acc[1][2 * p],     ah1, r0, r1);
            mma16816(acc[1][2 * p + 1], ah1, r2, r3);
        }
    }

    float* out;
    const float* bias;
    switch (which) {
        case 0: out = g_q;    bias = bq; break;
        case 1: out = g_k;    bias = bk; break;
        case 2: out = g_v;    bias = bv; break;
        case 3: out = g_base; bias = bs; break;
        default: out = g_xw;  bias = 0;  break;
    }
    const int rbase = row0 + 32 * wr + (lane >> 2);
    const int colb = 64 * wc + (lane & 3) * 2;
#pragma unroll
    for (int rg = 0; rg < 2; rg++) {
        const int r0i = rbase + 16 * rg;
        const bool ok0 = r0i < NN, ok1 = (r0i + 8) < NN;
#pragma unroll
        for (int nt = 0; nt < 8; nt++) {
            int col = nt * 8 + colb;
            float bx = 0.f, by = 0.f;
            if (bias) { bx = __ldg(bias + col); by = __ldg(bias + col + 1); }
            float2 v0 = make_float2(acc[rg][nt][0] + bx, acc[rg][nt][1] + by);
            float2 v1 = make_float2(acc[rg][nt][2] + bx, acc[rg][nt][3] + by);
            if (which == 3) {
                if (ok0) {
                    float2 xv = *(const float2*)(x + (size_t)r0i * DD + col);
                    v0.x += xv.x; v0.y += xv.y;
                }
                if (ok1) {
                    float2 xv = *(const float2*)(x + (size_t)(r0i + 8) * DD + col);
                    v1.x += xv.x; v1.y += xv.y;
                }
            }
            if (ok0) *(float2*)(out + (size_t)r0i * DD + col) = v0;
            if (ok1) *(float2*)(out + (size_t)(r0i + 8) * DD + col) = v1;
        }
    }
}

// ---------------- K2: fused per-node attention + GCN + LN + ReLU ----------
// Exact R9 version (best measured): warp per node; lane = 4 channels.
__global__ void __launch_bounds__(256)
k_fused(const float* __restrict__ bgcn,
        const float* __restrict__ gamma,
        const float* __restrict__ beta,
        float* __restrict__ out) {
    int i = blockIdx.x * 8 + (threadIdx.x >> 5);
    if (i >= NN) return;
    const int lane = threadIdx.x & 31;
    const int c4 = lane * 4;
    const int head = lane >> 4;

    const int off = g_off[i];
    const int deg = g_deg[i];
    const int end = off + deg;
    const float dis_i = g_dis[i];

    float4 qv = *(const float4*)(g_q + (size_t)i * DD + c4);

    // ---- loop 1: logits -> ex, per-lane denominator ----
    float den = 0.f;
    for (int base = off; base < end; base += 32) {
        int cnt = min(32, end - base);
        int myidx = (lane < cnt) ? __ldg(g_es + base + lane) : 0;
        for (int j = 0; j < cnt; j++) {
            int src = __shfl_sync(0xffffffffu, myidx, j);
            float4 kv = *(const float4*)(g_k + (size_t)src * DD + c4);
            float s = qv.x * kv.x + qv.y * kv.y + qv.z * kv.z + qv.w * kv.w;
            s += __shfl_xor_sync(0xffffffffu, s, 8);
            s += __shfl_xor_sync(0xffffffffu, s, 4);
            s += __shfl_xor_sync(0xffffffffu, s, 2);
            s += __shfl_xor_sync(0xffffffffu, s, 1);
            float ex = __expf(s * 0.125f);   // / sqrt(64)
            den += ex;                        // per-lane copy of its head's den
            float ex1 = __shfl_sync(0xffffffffu, ex, 16);
            if (lane == 0)
                *(float2*)(g_ex + (size_t)(base + j) * 2) = make_float2(ex, ex1);
        }
    }
    den += 1e-16f;

    // ---- loop 2: alpha-weighted V + norm-weighted XW accumulation ----
    float4 acc = make_float4(0.f, 0.f, 0.f, 0.f);
    for (int base = off; base < end; base += 32) {
        int cnt = min(32, end - base);
        int myidx = 0;
        float2 myex = make_float2(0.f, 0.f);
        if (lane < cnt) {
            myidx = __ldg(g_es + base + lane);
            myex = *(const float2*)(g_ex + (size_t)(base + lane) * 2);
        }
        for (int j = 0; j < cnt; j++) {
            int src = __shfl_sync(0xffffffffu, myidx, j);
            float e0 = __shfl_sync(0xffffffffu, myex.x, j);
            float e1 = __shfl_sync(0xffffffffu, myex.y, j);
            float alpha = (head ? e1 : e0) / den;
            float w = g_dis[src] * dis_i;
            float4 vv = *(const float4*)(g_v + (size_t)src * DD + c4);
            float4 xv = *(const float4*)(g_xw + (size_t)src * DD + c4);
            acc.x += alpha * vv.x + w * xv.x;
            acc.y += alpha * vv.y + w * xv.y;
            acc.z += alpha * vv.z + w * xv.z;
            acc.w += alpha * vv.w + w * xv.w;
        }
    }

    // ---- finalize: base + self-loop + LayerNorm + ReLU ----
    float4 b = *(const float4*)(g_base + (size_t)i * DD + c4);
    float4 xv = *(const float4*)(g_xw + (size_t)i * DD + c4);
    float4 bg = *(const float4*)(bgcn + c4);
    float d2 = dis_i * dis_i;

    float v0 = b.x + acc.x + d2 * xv.x + bg.x;
    float v1 = b.y + acc.y + d2 * xv.y + bg.y;
    float v2 = b.z + acc.z + d2 * xv.z + bg.z;
    float v3 = b.w + acc.w + d2 * xv.w + bg.w;

    float s = v0 + v1 + v2 + v3;
#pragma unroll
    for (int o = 16; o > 0; o >>= 1) s += __shfl_xor_sync(0xffffffffu, s, o);
    float mu = s * (1.0f / 128.0f);

    float d0 = v0 - mu, d1 = v1 - mu, d2_ = v2 - mu, d3 = v3 - mu;
    float sq = d0 * d0 + d1 * d1 + d2_ * d2_ + d3 * d3;
#pragma unroll
    for (int o = 16; o > 0; o >>= 1) sq += __shfl_xor_sync(0xffffffffu, sq, o);
    float inv = rsqrtf(sq * (1.0f / 128.0f) + 1e-5f);

    float4 g = *(const float4*)(gamma + c4);
    float4 be = *(const float4*)(beta + c4);
    float4 o4;
    o4.x = fmaxf(d0 * inv * g.x + be.x, 0.0f);
    o4.y = fmaxf(d1 * inv * g.y + be.y, 0.0f);
    o4.z = fmaxf(d2_ * inv * g.z + be.z, 0.0f);
    o4.w = fmaxf(d3 * inv * g.w + be.w, 0.0f);
    *(float4*)(out + (size_t)i * DD + c4) = o4;
}

// ---------------- launch ----------------
extern "C" void kernel_launch(void* const* d_in, const int* in_sizes, int n_in,
                              void* d_out, int out_size) {
    const float* x     = (const float*)d_in[0];
    const int*   ei    = (const int*)d_in[1];
    const float* Wq    = (const float*)d_in[2];
    const float* bq    = (const float*)d_in[3];
    const float* Wk    = (const float*)d_in[4];
    const float* bk    = (const float*)d_in[5];
    const float* Wv    = (const float*)d_in[6];
    const float* bv    = (const float*)d_in[7];
    const float* Wskip = (const float*)d_in[8];
    const float* bskip = (const float*)d_in[9];
    const float* Wgcn  = (const float*)d_in[10];
    const float* bgcn  = (const float*)d_in[11];
    const float* gamma = (const float*)d_in[12];
    const float* beta  = (const float*)d_in[13];
    float* out = (float*)d_out;

    static cudaEvent_t ev_fork = 0, ev_join = 0;
    if (!ev_fork) {
        cudaEventCreateWithFlags(&ev_fork, cudaEventDisableTiming);
        cudaEventCreateWithFlags(&ev_join, cudaEventDisableTiming);
        cudaFuncSetAttribute(k_gemm_mma,
                             cudaFuncAttributeMaxDynamicSharedMemorySize, GSMEM);
    }

    // Fork: CSR-build chain on the per-thread stream, overlapping the
    // prep+GEMM chain on the default stream. Join before k_fused.
    cudaEventRecord(ev_fork, 0);
    cudaStreamWaitEvent(cudaStreamPerThread, ev_fork, 0);
    k_init<<<(NN + 255) / 256, 256, 0, cudaStreamPerThread>>>();
    k_deg<<<(EE + 255) / 256, 256, 0, cudaStreamPerThread>>>(ei);
    k_node<<<(NN + 255) / 256, 256, 0, cudaStreamPerThread>>>();
    k_scatter<<<(EE + 255) / 256, 256, 0, cudaStreamPerThread>>>(ei);
    cudaEventRecord(ev_join, cudaStreamPerThread);

    k_prep_x<<<(NP * DD / 4 + 255) / 256, 256>>>(x);
    k_prep_w<<<(5 * DD * DD + 255) / 256, 256>>>(Wq, Wk, Wv, Wskip, Wgcn);
    dim3 ggrid(NRB, 5);
    k_gemm_mma<<<ggrid, 512, GSMEM>>>(x, bq, bk, bv, bskip);

    cudaStreamWaitEvent(0, ev_join, 0);
    k_fused<<<(NN + 7) / 8, 256>>>(bgcn, gamma, beta, out);
}

// round 15
// speedup vs baseline: 1.1006x; 1.0453x over previous
#include <cuda_runtime.h>
#include <cuda_bf16.h>
#include <cuda_fp16.h>
#include <cstdint>
#include <math.h>

#define NN 100000
#define NP 100096   /* 391 * 256 */
#define DD 128
#define HH 2
#define EE 640000
#define NRB 391     /* row blocks of 256 */

// ---------------- scratch (device globals; no runtime allocation) ----------
__device__ float g_q[NP * DD];
__device__ float g_base[NP * DD];
__device__ __align__(16) __half g_kh[NP * DD];   // fp16 gather copies
__device__ __align__(16) __half g_vh[NP * DD];
__device__ __align__(16) __half g_xh[NP * DD];
__device__ float g_ex[EE * HH];   // (ex_h0, ex_h1) per dst-sorted edge
__device__ float g_dis[NN];
__device__ int   g_deg[NN];
__device__ int   g_off[NN];
__device__ int   g_cur[NN];
__device__ int   g_es[EE];        // dst-sorted src indices
__device__ int   g_ctr;
__device__ __align__(16) __nv_bfloat16 g_xhi[NP * DD];
__device__ __align__(16) __nv_bfloat16 g_xlo[NP * DD];
__device__ __align__(16) __nv_bfloat16 g_whi[5 * DD * DD];  // transposed [which][n][k]
__device__ __align__(16) __nv_bfloat16 g_wlo[5 * DD * DD];

// ---------------- helpers ----------------
__device__ __forceinline__ uint32_t smem_u32(const void* p) {
    uint32_t a;
    asm("{ .reg .u64 t; cvta.to.shared.u64 t, %1; cvt.u32.u64 %0, t; }"
        : "=r"(a) : "l"(p));
    return a;
}
__device__ __forceinline__ void ldsm4(uint32_t& r0, uint32_t& r1, uint32_t& r2,
                                      uint32_t& r3, uint32_t addr) {
    asm volatile("ldmatrix.sync.aligned.m8n8.x4.shared.b16 {%0,%1,%2,%3}, [%4];"
                 : "=r"(r0), "=r"(r1), "=r"(r2), "=r"(r3) : "r"(addr));
}
__device__ __forceinline__ void mma16816(float* c, const uint32_t* a,
                                         uint32_t b0, uint32_t b1) {
    asm volatile(
        "mma.sync.aligned.m16n8k16.row.col.f32.bf16.bf16.f32 "
        "{%0,%1,%2,%3}, {%4,%5,%6,%7}, {%8,%9}, {%0,%1,%2,%3};"
        : "+f"(c[0]), "+f"(c[1]), "+f"(c[2]), "+f"(c[3])
        : "r"(a[0]), "r"(a[1]), "r"(a[2]), "r"(a[3]), "r"(b0), "r"(b1));
}

// ---------------- K0: init scratch ----------------
__global__ void k_init() {
    int i = blockIdx.x * blockDim.x + threadIdx.x;
    if (i < NN) { g_deg[i] = 0; g_cur[i] = 0; }
    if (i == 0) g_ctr = 0;
}

// ---------------- K_deg: degree count ----------------
__global__ void k_deg(const int* __restrict__ ei) {
    int e = blockIdx.x * blockDim.x + threadIdx.x;
    if (e >= EE) return;
    atomicAdd(&g_deg[__ldg(ei + EE + e)], 1);
}

// ---------------- K_node: offsets (warp-aggregated alloc) + dis ----------
__global__ void k_node() {
    int i = blockIdx.x * blockDim.x + threadIdx.x;
    int lane = threadIdx.x & 31;
    int d = (i < NN) ? g_deg[i] : 0;
    int incl = d;
#pragma unroll
    for (int o = 1; o < 32; o <<= 1) {
        int n = __shfl_up_sync(0xffffffffu, incl, o);
        if (lane >= o) incl += n;
    }
    int base = 0;
    if (lane == 31) base = atomicAdd(&g_ctr, incl);
    base = __shfl_sync(0xffffffffu, base, 31);
    if (i < NN) {
        g_off[i] = base + incl - d;
        g_dis[i] = rsqrtf((float)d + 1.0f);
    }
}

// ---------------- K_scatter: build dst-sorted src list ----------------
__global__ void k_scatter(const int* __restrict__ ei) {
    int e = blockIdx.x * blockDim.x + threadIdx.x;
    if (e >= EE) return;
    int dst = __ldg(ei + EE + e);
    int pos = g_off[dst] + atomicAdd(&g_cur[dst], 1);
    g_es[pos] = __ldg(ei + e);
}

// ---------------- K_prep: hi/lo bf16 split of x (padded) ----------------
__global__ void k_prep_x(const float* __restrict__ x) {
    int i = blockIdx.x * blockDim.x + threadIdx.x;  // per 4 elems
    if (i >= NP * DD / 4) return;
    float4 v = make_float4(0.f, 0.f, 0.f, 0.f);
    if (i < NN * DD / 4) v = ((const float4*)x)[i];
    float a[4] = {v.x, v.y, v.z, v.w};
    unsigned short h[4], l[4];
#pragma unroll
    for (int j = 0; j < 4; j++) {
        __nv_bfloat16 hb = __float2bfloat16(a[j]);
        __nv_bfloat16 lb = __float2bfloat16(a[j] - __bfloat162float(hb));
        h[j] = __bfloat16_as_ushort(hb);
        l[j] = __bfloat16_as_ushort(lb);
    }
    ((ushort4*)g_xhi)[i] = make_ushort4(h[0], h[1], h[2], h[3]);
    ((ushort4*)g_xlo)[i] = make_ushort4(l[0], l[1], l[2], l[3]);
}

// ---------------- K_prep: transpose + hi/lo split of the 5 weights -------
__global__ void k_prep_w(const float* __restrict__ Wq, const float* __restrict__ Wk,
                         const float* __restrict__ Wv, const float* __restrict__ Ws,
                         const float* __restrict__ Wg) {
    int i = blockIdx.x * blockDim.x + threadIdx.x;
    if (i >= 5 * DD * DD) return;
    int which = i >> 14;
    int r = i & 16383;
    int n = r >> 7, k = r & 127;
    const float* W;
    switch (which) {
        case 0: W = Wq; break; case 1: W = Wk; break; case 2: W = Wv; break;
        case 3: W = Ws; break; default: W = Wg; break;
    }
    float v = W[k * DD + n];  // transposed: Wt[n][k] = W[k][n]
    __nv_bfloat16 hb = __float2bfloat16(v);
    __nv_bfloat16 lb = __float2bfloat16(v - __bfloat162float(hb));
    g_whi[i] = hb;
    g_wlo[i] = lb;
}

// ---------------- swizzled tile loaders (512 threads) ---------------------
__device__ __forceinline__ void load_x_tile(char* dst, const __nv_bfloat16* src, int t) {
#pragma unroll
    for (int i = 0; i < 8; i++) {
        int idx = i * 512 + t;
        int row = idx >> 4;
        int kc = idx & 15;
        uint32_t off = (uint32_t)(row * 256 + ((kc ^ (row & 7)) << 4));
        *(uint4*)(dst + off) = *(const uint4*)((const char*)src + row * 256 + kc * 16);
    }
}
__device__ __forceinline__ void load_w_tile(char* dst, const __nv_bfloat16* src, int t) {
#pragma unroll
    for (int i = 0; i < 4; i++) {
        int idx = i * 512 + t;
        int row = idx >> 4;
        int kc = idx & 15;
        uint32_t off = (uint32_t)(row * 256 + ((kc ^ (row & 7)) << 4));
        *(uint4*)(dst + off) = *(const uint4*)((const char*)src + row * 256 + kc * 16);
    }
}

// ---------------- K1: mma.sync GEMM, one weight per block ----------------
// q, base -> fp32; k, v, xw -> fp16 gather copies.
#define GS_XHI 0
#define GS_XLO 65536
#define GS_WHI 131072
#define GS_WLO 163840
#define GSMEM  196608

__global__ void __launch_bounds__(512, 1)
k_gemm_mma(const float* __restrict__ x,
           const float* __restrict__ bq, const float* __restrict__ bk,
           const float* __restrict__ bv, const float* __restrict__ bs) {
    extern __shared__ char smem[];
    uint32_t sb = smem_u32(smem);
    const int t = threadIdx.x;
    const int w = t >> 5, lane = t & 31;
    const int wr = w >> 1;
    const int wc = w & 1;
    const int row0 = blockIdx.x * 256;
    const int which = blockIdx.y;

    load_x_tile(smem + GS_XHI, g_xhi + (size_t)row0 * DD, t);
    load_x_tile(smem + GS_XLO, g_xlo + (size_t)row0 * DD, t);
    load_w_tile(smem + GS_WHI, g_whi + (size_t)which * DD * DD, t);
    load_w_tile(smem + GS_WLO, g_wlo + (size_t)which * DD * DD, t);
    __syncthreads();

    const int sub = lane >> 3;
    const int a_row = 32 * wr + (lane & 7) + ((sub & 1) << 3);
    const int a_kc2 = sub >> 1;
    const int ar7 = a_row & 7;
    const uint32_t a_off0 = (uint32_t)(a_row * 256);
    const uint32_t a_off1 = (uint32_t)((a_row + 16) * 256);
    const int b_n = 64 * wc + (lane & 7) + ((sub >> 1) << 3);
    const int b_kc2 = sub & 1;
    const int bn7 = b_n & 7;
    const uint32_t b_off = (uint32_t)(b_n * 256);

    float acc[2][8][4];
#pragma unroll
    for (int i = 0; i < 2; i++)
#pragma unroll
        for (int j = 0; j < 8; j++)
#pragma unroll
            for (int q = 0; q < 4; q++) acc[i][j][q] = 0.f;

#pragma unroll
    for (int s = 0; s < 8; s++) {
        const uint32_t akc = ((uint32_t)((2 * s + a_kc2) ^ ar7)) << 4;
        const uint32_t bkc = ((uint32_t)((2 * s + b_kc2) ^ bn7)) << 4;
        uint32_t ah0[4], ah1[4], al0[4], al1[4];
        ldsm4(ah0[0], ah0[1], ah0[2], ah0[3], sb + GS_XHI + a_off0 + akc);
        ldsm4(ah1[0], ah1[1], ah1[2], ah1[3], sb + GS_XHI + a_off1 + akc);
        ldsm4(al0[0], al0[1], al0[2], al0[3], sb + GS_XLO + a_off0 + akc);
        ldsm4(al1[0], al1[1], al1[2], al1[3], sb + GS_XLO + a_off1 + akc);
#pragma unroll
        for (int p = 0; p < 4; p++) {
            const uint32_t poff = (uint32_t)(p * 4096);
            uint32_t r0, r1, r2, r3;
            ldsm4(r0, r1, r2, r3, sb + GS_WHI + b_off + poff + bkc);
            mma16816(acc[0][2 * p],     ah0, r0, r1);
            mma16816(acc[0][2 * p + 1], ah0, r2, r3);
            mma16816(acc[1][2 * p],     ah1, r0, r1);
            mma16816(acc[1][2 * p + 1], ah1, r2, r3);
            mma16816(acc[0][2 * p],     al0, r0, r1);
            mma16816(acc[0][2 * p + 1], al0, r2, r3);
            mma16816(acc[1][2 * p],     al1, r0, r1);
            mma16816(acc[1][2 * p + 1], al1, r2, r3);
            ldsm4(r0, r1, r2, r3, sb + GS_WLO + b_off + poff + bkc);
            mma16816(acc[0][2 * p],     ah0, r0, r1);
            mma16816(acc[0][2 * p + 1], ah0, r2, r3);
            mma16816(acc[1][2 * p],     ah1, r0, r1);
            mma16816(acc[1][2 * p + 1], ah1, r2, r3);
        }
    }

    float* outf = 0;
    __half* outh = 0;
    const float* bias;
    switch (which) {
        case 0: outf = g_q;    bias = bq; break;
        case 1: outh = g_kh;   bias = bk; break;
        case 2: outh = g_vh;   bias = bv; break;
        case 3: outf = g_base; bias = bs; break;
        default: outh = g_xh;  bias = 0;  break;
    }
    const int rbase = row0 + 32 * wr + (lane >> 2);
    const int colb = 64 * wc + (lane & 3) * 2;
#pragma unroll
    for (int rg = 0; rg < 2; rg++) {
        const int r0i = rbase + 16 * rg;
        const bool ok0 = r0i < NN, ok1 = (r0i + 8) < NN;
#pragma unroll
        for (int nt = 0; nt < 8; nt++) {
            int col = nt * 8 + colb;
            float bx = 0.f, by = 0.f;
            if (bias) { bx = __ldg(bias + col); by = __ldg(bias + col + 1); }
            float2 v0 = make_float2(acc[rg][nt][0] + bx, acc[rg][nt][1] + by);
            float2 v1 = make_float2(acc[rg][nt][2] + bx, acc[rg][nt][3] + by);
            if (outf) {
                if (which == 3) {
                    if (ok0) {
                        float2 xv = *(const float2*)(x + (size_t)r0i * DD + col);
                        v0.x += xv.x; v0.y += xv.y;
                    }
                    if (ok1) {
                        float2 xv = *(const float2*)(x + (size_t)(r0i + 8) * DD + col);
                        v1.x += xv.x; v1.y += xv.y;
                    }
                }
                if (ok0) *(float2*)(outf + (size_t)r0i * DD + col) = v0;
                if (ok1) *(float2*)(outf + (size_t)(r0i + 8) * DD + col) = v1;
            } else {
                if (ok0) *(__half2*)(outh + (size_t)r0i * DD + col) =
                    __floats2half2_rn(v0.x, v0.y);
                if (ok1) *(__half2*)(outh + (size_t)(r0i + 8) * DD + col) =
                    __floats2half2_rn(v1.x, v1.y);
            }
        }
    }
}

// ---------------- K2: fused per-node attention + GCN + LN + ReLU ----------
// R9 structure; k/v/xw gathered as fp16 (half the bytes per edge).
__global__ void __launch_bounds__(256)
k_fused(const float* __restrict__ bgcn,
        const float* __restrict__ gamma,
        const float* __restrict__ beta,
        float* __restrict__ out) {
    int i = blockIdx.x * 8 + (threadIdx.x >> 5);
    if (i >= NN) return;
    const int lane = threadIdx.x & 31;
    const int c4 = lane * 4;
    const int head = lane >> 4;

    const int off = g_off[i];
    const int deg = g_deg[i];
    const int end = off + deg;
    const float dis_i = g_dis[i];

    float4 qv = *(const float4*)(g_q + (size_t)i * DD + c4);

    // ---- loop 1: logits -> ex, per-lane denominator ----
    float den = 0.f;
    for (int base = off; base < end; base += 32) {
        int cnt = min(32, end - base);
        int myidx = (lane < cnt) ? __ldg(g_es + base + lane) : 0;
        for (int j = 0; j < cnt; j++) {
            int src = __shfl_sync(0xffffffffu, myidx, j);
            uint2 kr = *(const uint2*)(g_kh + (size_t)src * DD + c4);
            float2 k0 = __half22float2(*(__half2*)&kr.x);
            float2 k1 = __half22float2(*(__half2*)&kr.y);
            float s = qv.x * k0.x + qv.y * k0.y + qv.z * k1.x + qv.w * k1.y;
            s += __shfl_xor_sync(0xffffffffu, s, 8);
            s += __shfl_xor_sync(0xffffffffu, s, 4);
            s += __shfl_xor_sync(0xffffffffu, s, 2);
            s += __shfl_xor_sync(0xffffffffu, s, 1);
            float ex = __expf(s * 0.125f);   // / sqrt(64)
            den += ex;                        // per-lane copy of its head's den
            float ex1 = __shfl_sync(0xffffffffu, ex, 16);
            if (lane == 0)
                *(float2*)(g_ex + (size_t)(base + j) * 2) = make_float2(ex, ex1);
        }
    }
    den += 1e-16f;

    // ---- loop 2: alpha-weighted V + norm-weighted XW accumulation ----
    float4 acc = make_float4(0.f, 0.f, 0.f, 0.f);
    for (int base = off; base < end; base += 32) {
        int cnt = min(32, end - base);
        int myidx = 0;
        float2 myex = make_float2(0.f, 0.f);
        if (lane < cnt) {
            myidx = __ldg(g_es + base + lane);
            myex = *(const float2*)(g_ex + (size_t)(base + lane) * 2);
        }
        for (int j = 0; j < cnt; j++) {
            int src = __shfl_sync(0xffffffffu, myidx, j);
            float e0 = __shfl_sync(0xffffffffu, myex.x, j);
            float e1 = __shfl_sync(0xffffffffu, myex.y, j);
            float alpha = (head ? e1 : e0) / den;
            float w = g_dis[src] * dis_i;
            uint2 vr = *(const uint2*)(g_vh + (size_t)src * DD + c4);
            uint2 xr = *(const uint2*)(g_xh + (size_t)src * DD + c4);
            float2 v0 = __half22float2(*(__half2*)&vr.x);
            float2 v1 = __half22float2(*(__half2*)&vr.y);
            float2 x0 = __half22float2(*(__half2*)&xr.x);
            float2 x1 = __half22float2(*(__half2*)&xr.y);
            acc.x += alpha * v0.x + w * x0.x;
            acc.y += alpha * v0.y + w * x0.y;
            acc.z += alpha * v1.x + w * x1.x;
            acc.w += alpha * v1.y + w * x1.y;
        }
    }

    // ---- finalize: base + self-loop + LayerNorm + ReLU ----
    float4 b = *(const float4*)(g_base + (size_t)i * DD + c4);
    uint2 xr = *(const uint2*)(g_xh + (size_t)i * DD + c4);
    float2 xs0 = __half22float2(*(__half2*)&xr.x);
    float2 xs1 = __half22float2(*(__half2*)&xr.y);
    float4 bg = *(const float4*)(bgcn + c4);
    float d2 = dis_i * dis_i;

    float v0 = b.x + acc.x + d2 * xs0.x + bg.x;
    float v1 = b.y + acc.y + d2 * xs0.y + bg.y;
    float v2 = b.z + acc.z + d2 * xs1.x + bg.z;
    float v3 = b.w + acc.w + d2 * xs1.y + bg.w;

    float s = v0 + v1 + v2 + v3;
#pragma unroll
    for (int o = 16; o > 0; o >>= 1) s += __shfl_xor_sync(0xffffffffu, s, o);
    float mu = s * (1.0f / 128.0f);

    float d0 = v0 - mu, d1 = v1 - mu, d2_ = v2 - mu, d3 = v3 - mu;
    float sq = d0 * d0 + d1 * d1 + d2_ * d2_ + d3 * d3;
#pragma unroll
    for (int o = 16; o > 0; o >>= 1) sq += __shfl_xor_sync(0xffffffffu, sq, o);
    float inv = rsqrtf(sq * (1.0f / 128.0f) + 1e-5f);

    float4 g = *(const float4*)(gamma + c4);
    float4 be = *(const float4*)(beta + c4);
    float4 o4;
    o4.x = fmaxf(d0 * inv * g.x + be.x, 0.0f);
    o4.y = fmaxf(d1 * inv * g.y + be.y, 0.0f);
    o4.z = fmaxf(d2_ * inv * g.z + be.z, 0.0f);
    o4.w = fmaxf(d3 * inv * g.w + be.w, 0.0f);
    *(float4*)(out + (size_t)i * DD + c4) = o4;
}

// ---------------- launch ----------------
extern "C" void kernel_launch(void* const* d_in, const int* in_sizes, int n_in,
                              void* d_out, int out_size) {
    const float* x     = (const float*)d_in[0];
    const int*   ei    = (const int*)d_in[1];
    const float* Wq    = (const float*)d_in[2];
    const float* bq    = (const float*)d_in[3];
    const float* Wk    = (const float*)d_in[4];
    const float* bk    = (const float*)d_in[5];
    const float* Wv    = (const float*)d_in[6];
    const float* bv    = (const float*)d_in[7];
    const float* Wskip = (const float*)d_in[8];
    const float* bskip = (const float*)d_in[9];
    const float* Wgcn  = (const float*)d_in[10];
    const float* bgcn  = (const float*)d_in[11];
    const float* gamma = (const float*)d_in[12];
    const float* beta  = (const float*)d_in[13];
    float* out = (float*)d_out;

    static cudaEvent_t ev_fork = 0, ev_join = 0;
    if (!ev_fork) {
        cudaEventCreateWithFlags(&ev_fork, cudaEventDisableTiming);
        cudaEventCreateWithFlags(&ev_join, cudaEventDisableTiming);
        cudaFuncSetAttribute(k_gemm_mma,
                             cudaFuncAttributeMaxDynamicSharedMemorySize, GSMEM);
    }

    // Fork: CSR-build chain on the per-thread stream, overlapping the
    // prep+GEMM chain on the default stream. Join before k_fused.
    cudaEventRecord(ev_fork, 0);
    cudaStreamWaitEvent(cudaStreamPerThread, ev_fork, 0);
    k_init<<<(NN + 255) / 256, 256, 0, cudaStreamPerThread>>>();
    k_deg<<<(EE + 255) / 256, 256, 0, cudaStreamPerThread>>>(ei);
    k_node<<<(NN + 255) / 256, 256, 0, cudaStreamPerThread>>>();
    k_scatter<<<(EE + 255) / 256, 256, 0, cudaStreamPerThread>>>(ei);
    cudaEventRecord(ev_join, cudaStreamPerThread);

    k_prep_x<<<(NP * DD / 4 + 255) / 256, 256>>>(x);
    k_prep_w<<<(5 * DD * DD + 255) / 256, 256>>>(Wq, Wk, Wv, Wskip, Wgcn);
    dim3 ggrid(NRB, 5);
    k_gemm_mma<<<ggrid, 512, GSMEM>>>(x, bq, bk, bv, bskip);

    cudaStreamWaitEvent(0, ev_join, 0);
    k_fused<<<(NN + 7) / 8, 256>>>(bgcn, gamma, beta, out);
}

// round 16
// speedup vs baseline: 1.1639x; 1.0575x over previous
#include <cuda_runtime.h>
#include <cuda_bf16.h>
#include <cuda_fp16.h>
#include <cstdint>
#include <math.h>

#define NN 100000
#define NP 100096   /* 391 * 256 */
#define DD 128
#define HH 2
#define EE 640000
#define NRB 391     /* row blocks of 256 */

// ---------------- scratch (device globals; no runtime allocation) ----------
__device__ float g_q[NP * DD];
__device__ float g_base[NP * DD];
__device__ __align__(16) __half g_kh[NP * DD];       // fp16 k gather copy
__device__ __align__(16) __half g_vxh[NP * DD * 2];  // interleaved v|xw per 4-ch group
__device__ float g_dis[NN];
__device__ int   g_deg[NN];
__device__ int   g_off[NN];
__device__ int   g_cur[NN];
__device__ int   g_es[EE];        // dst-sorted src indices
__device__ int   g_ctr;
__device__ __align__(16) __nv_bfloat16 g_xhi[NP * DD];
__device__ __align__(16) __nv_bfloat16 g_xlo[NP * DD];
__device__ __align__(16) __nv_bfloat16 g_whi[5 * DD * DD];  // transposed [which][n][k]
__device__ __align__(16) __nv_bfloat16 g_wlo[5 * DD * DD];

// ---------------- helpers ----------------
__device__ __forceinline__ uint32_t smem_u32(const void* p) {
    uint32_t a;
    asm("{ .reg .u64 t; cvta.to.shared.u64 t, %1; cvt.u32.u64 %0, t; }"
        : "=r"(a) : "l"(p));
    return a;
}
__device__ __forceinline__ void ldsm4(uint32_t& r0, uint32_t& r1, uint32_t& r2,
                                      uint32_t& r3, uint32_t addr) {
    asm volatile("ldmatrix.sync.aligned.m8n8.x4.shared.b16 {%0,%1,%2,%3}, [%4];"
                 : "=r"(r0), "=r"(r1), "=r"(r2), "=r"(r3) : "r"(addr));
}
__device__ __forceinline__ void mma16816(float* c, const uint32_t* a,
                                         uint32_t b0, uint32_t b1) {
    asm volatile(
        "mma.sync.aligned.m16n8k16.row.col.f32.bf16.bf16.f32 "
        "{%0,%1,%2,%3}, {%4,%5,%6,%7}, {%8,%9}, {%0,%1,%2,%3};"
        : "+f"(c[0]), "+f"(c[1]), "+f"(c[2]), "+f"(c[3])
        : "r"(a[0]), "r"(a[1]), "r"(a[2]), "r"(a[3]), "r"(b0), "r"(b1));
}

// ---------------- K0: init scratch ----------------
__global__ void k_init() {
    int i = blockIdx.x * blockDim.x + threadIdx.x;
    if (i < NN) { g_deg[i] = 0; g_cur[i] = 0; }
    if (i == 0) g_ctr = 0;
}

// ---------------- K_deg: degree count ----------------
__global__ void k_deg(const int* __restrict__ ei) {
    int e = blockIdx.x * blockDim.x + threadIdx.x;
    if (e >= EE) return;
    atomicAdd(&g_deg[__ldg(ei + EE + e)], 1);
}

// ---------------- K_node: offsets (warp-aggregated alloc) + dis ----------
__global__ void k_node() {
    int i = blockIdx.x * blockDim.x + threadIdx.x;
    int lane = threadIdx.x & 31;
    int d = (i < NN) ? g_deg[i] : 0;
    int incl = d;
#pragma unroll
    for (int o = 1; o < 32; o <<= 1) {
        int n = __shfl_up_sync(0xffffffffu, incl, o);
        if (lane >= o) incl += n;
    }
    int base = 0;
    if (lane == 31) base = atomicAdd(&g_ctr, incl);
    base = __shfl_sync(0xffffffffu, base, 31);
    if (i < NN) {
        g_off[i] = base + incl - d;
        g_dis[i] = rsqrtf((float)d + 1.0f);
    }
}

// ---------------- K_scatter: build dst-sorted src list ----------------
__global__ void k_scatter(const int* __restrict__ ei) {
    int e = blockIdx.x * blockDim.x + threadIdx.x;
    if (e >= EE) return;
    int dst = __ldg(ei + EE + e);
    int pos = g_off[dst] + atomicAdd(&g_cur[dst], 1);
    g_es[pos] = __ldg(ei + e);
}

// ---------------- K_prep: hi/lo bf16 split of x (padded) ----------------
__global__ void k_prep_x(const float* __restrict__ x) {
    int i = blockIdx.x * blockDim.x + threadIdx.x;  // per 4 elems
    if (i >= NP * DD / 4) return;
    float4 v = make_float4(0.f, 0.f, 0.f, 0.f);
    if (i < NN * DD / 4) v = ((const float4*)x)[i];
    float a[4] = {v.x, v.y, v.z, v.w};
    unsigned short h[4], l[4];
#pragma unroll
    for (int j = 0; j < 4; j++) {
        __nv_bfloat16 hb = __float2bfloat16(a[j]);
        __nv_bfloat16 lb = __float2bfloat16(a[j] - __bfloat162float(hb));
        h[j] = __bfloat16_as_ushort(hb);
        l[j] = __bfloat16_as_ushort(lb);
    }
    ((ushort4*)g_xhi)[i] = make_ushort4(h[0], h[1], h[2], h[3]);
    ((ushort4*)g_xlo)[i] = make_ushort4(l[0], l[1], l[2], l[3]);
}

// ---------------- K_prep: transpose + hi/lo split of the 5 weights -------
__global__ void k_prep_w(const float* __restrict__ Wq, const float* __restrict__ Wk,
                         const float* __restrict__ Wv, const float* __restrict__ Ws,
                         const float* __restrict__ Wg) {
    int i = blockIdx.x * blockDim.x + threadIdx.x;
    if (i >= 5 * DD * DD) return;
    int which = i >> 14;
    int r = i & 16383;
    int n = r >> 7, k = r & 127;
    const float* W;
    switch (which) {
        case 0: W = Wq; break; case 1: W = Wk; break; case 2: W = Wv; break;
        case 3: W = Ws; break; default: W = Wg; break;
    }
    float v = W[k * DD + n];  // transposed: Wt[n][k] = W[k][n]
    __nv_bfloat16 hb = __float2bfloat16(v);
    __nv_bfloat16 lb = __float2bfloat16(v - __bfloat162float(hb));
    g_whi[i] = hb;
    g_wlo[i] = lb;
}

// ---------------- swizzled tile loaders (512 threads) ---------------------
__device__ __forceinline__ void load_x_tile(char* dst, const __nv_bfloat16* src, int t) {
#pragma unroll
    for (int i = 0; i < 8; i++) {
        int idx = i * 512 + t;
        int row = idx >> 4;
        int kc = idx & 15;
        uint32_t off = (uint32_t)(row * 256 + ((kc ^ (row & 7)) << 4));
        *(uint4*)(dst + off) = *(const uint4*)((const char*)src + row * 256 + kc * 16);
    }
}
__device__ __forceinline__ void load_w_tile(char* dst, const __nv_bfloat16* src, int t) {
#pragma unroll
    for (int i = 0; i < 4; i++) {
        int idx = i * 512 + t;
        int row = idx >> 4;
        int kc = idx & 15;
        uint32_t off = (uint32_t)(row * 256 + ((kc ^ (row & 7)) << 4));
        *(uint4*)(dst + off) = *(const uint4*)((const char*)src + row * 256 + kc * 16);
    }
}

// ---------------- K1: mma.sync GEMM, one weight per block ----------------
// q, base -> fp32; k -> g_kh fp16; v/xw -> interleaved g_vxh fp16.
#define GS_XHI 0
#define GS_XLO 65536
#define GS_WHI 131072
#define GS_WLO 163840
#define GSMEM  196608

__global__ void __launch_bounds__(512, 1)
k_gemm_mma(const float* __restrict__ x,
           const float* __restrict__ bq, const float* __restrict__ bk,
           const float* __restrict__ bv, const float* __restrict__ bs) {
    extern __shared__ char smem[];
    uint32_t sb = smem_u32(smem);
    const int t = threadIdx.x;
    const int w = t >> 5, lane = t & 31;
    const int wr = w >> 1;
    const int wc = w & 1;
    const int row0 = blockIdx.x * 256;
    const int which = blockIdx.y;

    load_x_tile(smem + GS_XHI, g_xhi + (size_t)row0 * DD, t);
    load_x_tile(smem + GS_XLO, g_xlo + (size_t)row0 * DD, t);
    load_w_tile(smem + GS_WHI, g_whi + (size_t)which * DD * DD, t);
    load_w_tile(smem + GS_WLO, g_wlo + (size_t)which * DD * DD, t);
    __syncthreads();

    const int sub = lane >> 3;
    const int a_row = 32 * wr + (lane & 7) + ((sub & 1) << 3);
    const int a_kc2 = sub >> 1;
    const int ar7 = a_row & 7;
    const uint32_t a_off0 = (uint32_t)(a_row * 256);
    const uint32_t a_off1 = (uint32_t)((a_row + 16) * 256);
    const int b_n = 64 * wc + (lane & 7) + ((sub >> 1) << 3);
    const int b_kc2 = sub & 1;
    const int bn7 = b_n & 7;
    const uint32_t b_off = (uint32_t)(b_n * 256);

    float acc[2][8][4];
#pragma unroll
    for (int i = 0; i < 2; i++)
#pragma unroll
        for (int j = 0; j < 8; j++)
#pragma unroll
            for (int q = 0; q < 4; q++) acc[i][j][q] = 0.f;

#pragma unroll
    for (int s = 0; s < 8; s++) {
        const uint32_t akc = ((uint32_t)((2 * s + a_kc2) ^ ar7)) << 4;
        const uint32_t bkc = ((uint32_t)((2 * s + b_kc2) ^ bn7)) << 4;
        uint32_t ah0[4], ah1[4], al0[4], al1[4];
        ldsm4(ah0[0], ah0[1], ah0[2], ah0[3], sb + GS_XHI + a_off0 + akc);
        ldsm4(ah1[0], ah1[1], ah1[2], ah1[3], sb + GS_XHI + a_off1 + akc);
        ldsm4(al0[0], al0[1], al0[2], al0[3], sb + GS_XLO + a_off0 + akc);
        ldsm4(al1[0], al1[1], al1[2], al1[3], sb + GS_XLO + a_off1 + akc);
#pragma unroll
        for (int p = 0; p < 4; p++) {
            const uint32_t poff = (uint32_t)(p * 4096);
            uint32_t r0, r1, r2, r3;
            ldsm4(r0, r1, r2, r3, sb + GS_WHI + b_off + poff + bkc);
            mma16816(acc[0][2 * p],     ah0, r0, r1);
            mma16816(acc[0][2 * p + 1], ah0, r2, r3);
            mma16816(acc[1][2 * p],     ah1, r0, r1);
            mma16816(acc[1][2 * p + 1], ah1, r2, r3);
            mma16816(acc[0][2 * p],     al0, r0, r1);
            mma16816(acc[0][2 * p + 1], al0, r2, r3);
            mma16816(acc[1][2 * p],     al1, r0, r1);
            mma16816(acc[1][2 * p + 1], al1, r2, r3);
            ldsm4(r0, r1, r2, r3, sb + GS_WLO + b_off + poff + bkc);
            mma16816(acc[0][2 * p],     ah0, r0, r1);
            mma16816(acc[0][2 * p + 1], ah0, r2, r3);
            mma16816(acc[1][2 * p],     ah1, r0, r1);
            mma16816(acc[1][2 * p + 1], ah1, r2, r3);
        }
    }

    // epilogue
    float* outf = 0;
    const float* bias;
    int vx_sel = 0;   // 0 = v slot, 4 = xw slot (for g_vxh targets)
    bool to_vx = false, to_k = false;
    switch (which) {
        case 0: outf = g_q;    bias = bq; break;
        case 1: to_k = true;   bias = bk; break;
        case 2: to_vx = true;  vx_sel = 0; bias = bv; break;
        case 3: outf = g_base; bias = bs; break;
        default: to_vx = true; vx_sel = 4; bias = 0; break;
    }
    const int rbase = row0 + 32 * wr + (lane >> 2);
    const int colb = 64 * wc + (lane & 3) * 2;
#pragma unroll
    for (int rg = 0; rg < 2; rg++) {
        const int r0i = rbase + 16 * rg;
        const bool ok0 = r0i < NN, ok1 = (r0i + 8) < NN;
#pragma unroll
        for (int nt = 0; nt < 8; nt++) {
            int col = nt * 8 + colb;
            float bx = 0.f, by = 0.f;
            if (bias) { bx = __ldg(bias + col); by = __ldg(bias + col + 1); }
            float2 v0 = make_float2(acc[rg][nt][0] + bx, acc[rg][nt][1] + by);
            float2 v1 = make_float2(acc[rg][nt][2] + bx, acc[rg][nt][3] + by);
            if (outf) {
                if (which == 3) {
                    if (ok0) {
                        float2 xv = *(const float2*)(x + (size_t)r0i * DD + col);
                        v0.x += xv.x; v0.y += xv.y;
                    }
                    if (ok1) {
                        float2 xv = *(const float2*)(x + (size_t)(r0i + 8) * DD + col);
                        v1.x += xv.x; v1.y += xv.y;
                    }
                }
                if (ok0) *(float2*)(outf + (size_t)r0i * DD + col) = v0;
                if (ok1) *(float2*)(outf + (size_t)(r0i + 8) * DD + col) = v1;
            } else if (to_k) {
                if (ok0) *(__half2*)(g_kh + (size_t)r0i * DD + col) =
                    __floats2half2_rn(v0.x, v0.y);
                if (ok1) *(__half2*)(g_kh + (size_t)(r0i + 8) * DD + col) =
                    __floats2half2_rn(v1.x, v1.y);
            } else {
                // interleaved: 4-ch group layout [v0 v1 v2 v3 | x0 x1 x2 x3]
                size_t h0 = (size_t)r0i * 256 + (col >> 2) * 8 + (col & 3) + vx_sel;
                size_t h1 = (size_t)(r0i + 8) * 256 + (col >> 2) * 8 + (col & 3) + vx_sel;
                if (ok0) *(__half2*)(g_vxh + h0) = __floats2half2_rn(v0.x, v0.y);
                if (ok1) *(__half2*)(g_vxh + h1) = __floats2half2_rn(v1.x, v1.y);
            }
        }
    }
}

// ---------------- K2: fused SINGLE-PASS attention + GCN + LN + ReLU -------
// alpha = ex/den distributes: acc_v = sum(ex*v); result = acc_v/den.
// One edge loop: gather k (8B/lane) + interleaved v|xw (16B/lane).
__global__ void __launch_bounds__(256)
k_fused(const float* __restrict__ bgcn,
        const float* __restrict__ gamma,
        const float* __restrict__ beta,
        float* __restrict__ out) {
    int i = blockIdx.x * 8 + (threadIdx.x >> 5);
    if (i >= NN) return;
    const int lane = threadIdx.x & 31;
    const int c4 = lane * 4;

    const int off = g_off[i];
    const int deg = g_deg[i];
    const int end = off + deg;
    const float dis_i = g_dis[i];

    float4 qv = *(const float4*)(g_q + (size_t)i * DD + c4);

    float den = 0.f;
    float4 accv = make_float4(0.f, 0.f, 0.f, 0.f);
    float4 accx = make_float4(0.f, 0.f, 0.f, 0.f);

    for (int base = off; base < end; base += 32) {
        int cnt = min(32, end - base);
        int myidx = (lane < cnt) ? __ldg(g_es + base + lane) : 0;
        for (int j = 0; j < cnt; j++) {
            int src = __shfl_sync(0xffffffffu, myidx, j);
            uint2 kr = *(const uint2*)(g_kh + (size_t)src * DD + c4);
            float2 k0 = __half22float2(*(__half2*)&kr.x);
            float2 k1 = __half22float2(*(__half2*)&kr.y);
            float s = qv.x * k0.x + qv.y * k0.y + qv.z * k1.x + qv.w * k1.y;
            s += __shfl_xor_sync(0xffffffffu, s, 8);
            s += __shfl_xor_sync(0xffffffffu, s, 4);
            s += __shfl_xor_sync(0xffffffffu, s, 2);
            s += __shfl_xor_sync(0xffffffffu, s, 1);
            float ex = __expf(s * 0.125f);   // lane's own head
            den += ex;
            uint4 vxr = *(const uint4*)(g_vxh + (size_t)src * 256 + lane * 8);
            float2 v0 = __half22float2(*(__half2*)&vxr.x);
            float2 v1 = __half22float2(*(__half2*)&vxr.y);
            float2 x0 = __half22float2(*(__half2*)&vxr.z);
            float2 x1 = __half22float2(*(__half2*)&vxr.w);
            float w = g_dis[src] * dis_i;
            accv.x += ex * v0.x; accv.y += ex * v0.y;
            accv.z += ex * v1.x; accv.w += ex * v1.y;
            accx.x += w * x0.x;  accx.y += w * x0.y;
            accx.z += w * x1.x;  accx.w += w * x1.y;
        }
    }
    float rden = 1.0f / (den + 1e-16f);

    // ---- finalize: base + self-loop + LayerNorm + ReLU ----
    float4 b = *(const float4*)(g_base + (size_t)i * DD + c4);
    uint2 xr = *(const uint2*)(g_vxh + (size_t)i * 256 + lane * 8 + 4);
    float2 xs0 = __half22float2(*(__half2*)&xr.x);
    float2 xs1 = __half22float2(*(__half2*)&xr.y);
    float4 bg = *(const float4*)(bgcn + c4);
    float d2 = dis_i * dis_i;

    float v0 = b.x + accv.x * rden + accx.x + d2 * xs0.x + bg.x;
    float v1 = b.y + accv.y * rden + accx.y + d2 * xs0.y + bg.y;
    float v2 = b.z + accv.z * rden + accx.z + d2 * xs1.x + bg.z;
    float v3 = b.w + accv.w * rden + accx.w + d2 * xs1.y + bg.w;

    float s = v0 + v1 + v2 + v3;
#pragma unroll
    for (int o = 16; o > 0; o >>= 1) s += __shfl_xor_sync(0xffffffffu, s, o);
    float mu = s * (1.0f / 128.0f);

    float d0 = v0 - mu, d1 = v1 - mu, d2_ = v2 - mu, d3 = v3 - mu;
    float sq = d0 * d0 + d1 * d1 + d2_ * d2_ + d3 * d3;
#pragma unroll
    for (int o = 16; o > 0; o >>= 1) sq += __shfl_xor_sync(0xffffffffu, sq, o);
    float inv = rsqrtf(sq * (1.0f / 128.0f) + 1e-5f);

    float4 g = *(const float4*)(gamma + c4);
    float4 be = *(const float4*)(beta + c4);
    float4 o4;
    o4.x = fmaxf(d0 * inv * g.x + be.x, 0.0f);
    o4.y = fmaxf(d1 * inv * g.y + be.y, 0.0f);
    o4.z = fmaxf(d2_ * inv * g.z + be.z, 0.0f);
    o4.w = fmaxf(d3 * inv * g.w + be.w, 0.0f);
    *(float4*)(out + (size_t)i * DD + c4) = o4;
}

// ---------------- launch ----------------
extern "C" void kernel_launch(void* const* d_in, const int* in_sizes, int n_in,
                              void* d_out, int out_size) {
    const float* x     = (const float*)d_in[0];
    const int*   ei    = (const int*)d_in[1];
    const float* Wq    = (const float*)d_in[2];
    const float* bq    = (const float*)d_in[3];
    const float* Wk    = (const float*)d_in[4];
    const float* bk    = (const float*)d_in[5];
    const float* Wv    = (const float*)d_in[6];
    const float* bv    = (const float*)d_in[7];
    const float* Wskip = (const float*)d_in[8];
    const float* bskip = (const float*)d_in[9];
    const float* Wgcn  = (const float*)d_in[10];
    const float* bgcn  = (const float*)d_in[11];
    const float* gamma = (const float*)d_in[12];
    const float* beta  = (const float*)d_in[13];
    float* out = (float*)d_out;

    static cudaEvent_t ev_fork = 0, ev_join = 0;
    if (!ev_fork) {
        cudaEventCreateWithFlags(&ev_fork, cudaEventDisableTiming);
        cudaEventCreateWithFlags(&ev_join, cudaEventDisableTiming);
        cudaFuncSetAttribute(k_gemm_mma,
                             cudaFuncAttributeMaxDynamicSharedMemorySize, GSMEM);
    }

    // Fork: CSR-build chain on the per-thread stream, overlapping the
    // prep+GEMM chain on the default stream. Join before k_fused.
    cudaEventRecord(ev_fork, 0);
    cudaStreamWaitEvent(cudaStreamPerThread, ev_fork, 0);
    k_init<<<(NN + 255) / 256, 256, 0, cudaStreamPerThread>>>();
    k_deg<<<(EE + 255) / 256, 256, 0, cudaStreamPerThread>>>(ei);
    k_node<<<(NN + 255) / 256, 256, 0, cudaStreamPerThread>>>();
    k_scatter<<<(EE + 255) / 256, 256, 0, cudaStreamPerThread>>>(ei);
    cudaEventRecord(ev_join, cudaStreamPerThread);

    k_prep_x<<<(NP * DD / 4 + 255) / 256, 256>>>(x);
    k_prep_w<<<(5 * DD * DD + 255) / 256, 256>>>(Wq, Wk, Wv, Wskip, Wgcn);
    dim3 ggrid(NRB, 5);
    k_gemm_mma<<<ggrid, 512, GSMEM>>>(x, bq, bk, bv, bskip);

    cudaStreamWaitEvent(0, ev_join, 0);
    k_fused<<<(NN + 7) / 8, 256>>>(bgcn, gamma, beta, out);
}